// round 1
// baseline (speedup 1.0000x reference)
#include <cuda_runtime.h>
#include <cstdint>
#include <cstddef>

#define B_  256
#define T_  256
#define D_  128
#define H_  256
#define BT_ 65536

// Scratch (allocation-free rule: __device__ globals)
__device__ float g_h [(size_t)BT_ * H_];  // post-LN hidden  [BT,256]
__device__ float g_s1[(size_t)BT_ * H_];  // layer-1 spikes  [BT,256] (exact 0/1)
__device__ float g_o [(size_t)BT_ * D_];  // post-LN output  [BT,128]

// ---------- packed fp32x2 helpers (sm_103a FFMA2 path) ----------
__device__ __forceinline__ unsigned long long pack2(float x, float y) {
    unsigned long long r;
    asm("mov.b64 %0, {%1, %2};" : "=l"(r) : "f"(x), "f"(y));
    return r;
}
__device__ __forceinline__ float2 unpack2(unsigned long long v) {
    float2 f;
    asm("mov.b64 {%0, %1}, %2;" : "=f"(f.x), "=f"(f.y) : "l"(v));
    return f;
}
__device__ __forceinline__ void ffma2(unsigned long long& c,
                                      unsigned long long a,
                                      unsigned long long b) {
    asm("fma.rn.f32x2 %0, %1, %2, %3;" : "=l"(c) : "l"(a), "l"(b), "l"(c));
}

// =====================================================================
// Kernel 1: h_ln[row,h] = LN_h( x[row,:] @ W1[h,:] + b1[h] ) * g1 + be1
// tile: 128 rows x 256 cols (full H), K=128. 512 threads.
// warp ty owns rows ty*8..+7; lane tx owns cols tx*8..+7 (4 col-pairs).
// =====================================================================
__global__ __launch_bounds__(512, 1)
void gemm1_ln_kernel(const float* __restrict__ x, const float* __restrict__ W1,
                     const float* __restrict__ b1, const float* __restrict__ g1,
                     const float* __restrict__ be1)
{
    extern __shared__ float smem[];
    float* As = smem;              // [128][128] row-major (r,k)
    float* Bs = smem + 128 * 128;  // [128][256] k-major (k,h)
    const int tid  = threadIdx.x;
    const int row0 = blockIdx.x * 128;

    // stage x tile (straight vectorized copy, coalesced, conflict-free)
    {
        const int r  = tid >> 5;   // 0..15
        const int kq = tid & 31;   // 0..31
        #pragma unroll
        for (int p = 0; p < 8; ++p) {
            const int rr = p * 16 + r;
            float4 v = *reinterpret_cast<const float4*>(x + (size_t)(row0 + rr) * D_ + kq * 4);
            *reinterpret_cast<float4*>(As + rr * 128 + kq * 4) = v;
        }
    }
    // stage W1 transposed -> Bs[k][h]  (one-time 128KB)
    {
        const int h  = tid >> 1;   // 0..255
        const int q0 = tid & 1;
        #pragma unroll
        for (int p = 0; p < 16; ++p) {
            const int q = p * 2 + q0;  // 0..31 (k quad)
            float4 v = *reinterpret_cast<const float4*>(W1 + (size_t)h * D_ + q * 4);
            Bs[(q * 4 + 0) * 256 + h] = v.x;
            Bs[(q * 4 + 1) * 256 + h] = v.y;
            Bs[(q * 4 + 2) * 256 + h] = v.z;
            Bs[(q * 4 + 3) * 256 + h] = v.w;
        }
    }
    __syncthreads();

    const int ty = tid >> 5;
    const int tx = tid & 31;

    unsigned long long acc[8][4];
    #pragma unroll
    for (int i = 0; i < 8; ++i)
        #pragma unroll
        for (int j = 0; j < 4; ++j) acc[i][j] = 0ull;

    const float* arow  = As + (ty * 8) * 128;
    const float* bbase = Bs + tx * 8;

    #pragma unroll 4
    for (int k = 0; k < 128; ++k) {
        unsigned long long a2[8];
        #pragma unroll
        for (int i = 0; i < 8; ++i) {
            const float a = arow[i * 128 + k];   // broadcast LDS (free)
            a2[i] = pack2(a, a);
        }
        const longlong2* bp = reinterpret_cast<const longlong2*>(bbase + k * 256);
        const longlong2 bA = bp[0];
        const longlong2 bB = bp[1];
        unsigned long long bv[4] = {(unsigned long long)bA.x, (unsigned long long)bA.y,
                                    (unsigned long long)bB.x, (unsigned long long)bB.y};
        #pragma unroll
        for (int i = 0; i < 8; ++i)
            #pragma unroll
            for (int j = 0; j < 4; ++j) ffma2(acc[i][j], a2[i], bv[j]);
    }

    // LN epilogue: per-row warp allreduce over H=256
    const int h0 = tx * 8;
    float b1v[8], g1v[8], be1v[8];
    #pragma unroll
    for (int c = 0; c < 8; ++c) {
        b1v[c] = b1[h0 + c]; g1v[c] = g1[h0 + c]; be1v[c] = be1[h0 + c];
    }
    #pragma unroll
    for (int i = 0; i < 8; ++i) {
        float v[8];
        #pragma unroll
        for (int j = 0; j < 4; ++j) {
            const float2 f = unpack2(acc[i][j]);
            v[2 * j]     = f.x + b1v[2 * j];
            v[2 * j + 1] = f.y + b1v[2 * j + 1];
        }
        float s1 = 0.f, s2 = 0.f;
        #pragma unroll
        for (int c = 0; c < 8; ++c) { s1 += v[c]; s2 += v[c] * v[c]; }
        #pragma unroll
        for (int o = 16; o > 0; o >>= 1) {
            s1 += __shfl_xor_sync(0xffffffffu, s1, o);
            s2 += __shfl_xor_sync(0xffffffffu, s2, o);
        }
        const float m   = s1 * (1.0f / 256.0f);
        const float var = s2 * (1.0f / 256.0f) - m * m;
        const float inv = rsqrtf(var + 1e-5f);
        float ov[8];
        #pragma unroll
        for (int c = 0; c < 8; ++c) ov[c] = (v[c] - m) * inv * g1v[c] + be1v[c];
        const int row = row0 + ty * 8 + i;
        float4* dst = reinterpret_cast<float4*>(g_h + (size_t)row * H_ + h0);
        dst[0] = make_float4(ov[0], ov[1], ov[2], ov[3]);
        dst[1] = make_float4(ov[4], ov[5], ov[6], ov[7]);
    }
}

// =====================================================================
// Kernel 2: LIF scan over T per (b,h) lane. Matches reference rounding.
// =====================================================================
__global__ void lif1_kernel()
{
    const int b = blockIdx.x;
    const int h = threadIdx.x;           // 0..255
    const size_t base = (size_t)b * T_ * H_ + h;
    float v = 0.f;
    #pragma unroll 4
    for (int t = 0; t < T_; ++t) {
        const size_t idx = base + (size_t)t * H_;
        const float xv = g_h[idx];
        const float hm = v + (xv - v) * 0.5f;   // v + (x-v)/TAU, TAU=2
        const bool  s  = (hm >= 1.0f);
        g_s1[idx] = s ? 1.0f : 0.0f;
        v = s ? 0.0f : hm;
    }
}

// =====================================================================
// Kernel 3: o_ln[row,d] = LN_d( s1[row,:] @ W2[d,:] + b2[d] ) * g2 + be2
// tile: 64 rows x 128 cols (full D), K=256. 512 threads.
// warp ty owns rows ty*4..+3; lane tx owns cols tx*4..+3 (2 col-pairs).
// =====================================================================
__global__ __launch_bounds__(512, 1)
void gemm2_ln_kernel(const float* __restrict__ W2, const float* __restrict__ b2,
                     const float* __restrict__ g2, const float* __restrict__ be2)
{
    extern __shared__ float smem[];
    float* As = smem;             // [64][256] row-major (r,k)
    float* Bs = smem + 64 * 256;  // [256][128] k-major (k,d)
    const int tid  = threadIdx.x;
    const int row0 = blockIdx.x * 64;

    // stage spike tile (straight copy)
    {
        const int r  = tid >> 6;   // 0..7
        const int kq = tid & 63;   // 0..63
        #pragma unroll
        for (int p = 0; p < 8; ++p) {
            const int rr = p * 8 + r;
            float4 v = *reinterpret_cast<const float4*>(g_s1 + (size_t)(row0 + rr) * H_ + kq * 4);
            *reinterpret_cast<float4*>(As + rr * 256 + kq * 4) = v;
        }
    }
    // stage W2 transposed -> Bs[k][d]
    {
        const int d  = tid >> 2;   // 0..127
        const int q0 = tid & 3;
        #pragma unroll
        for (int p = 0; p < 16; ++p) {
            const int q = p * 4 + q0;  // 0..63 (k quad)
            float4 v = *reinterpret_cast<const float4*>(W2 + (size_t)d * H_ + q * 4);
            Bs[(q * 4 + 0) * 128 + d] = v.x;
            Bs[(q * 4 + 1) * 128 + d] = v.y;
            Bs[(q * 4 + 2) * 128 + d] = v.z;
            Bs[(q * 4 + 3) * 128 + d] = v.w;
        }
    }
    __syncthreads();

    const int ty = tid >> 5;
    const int tx = tid & 31;

    unsigned long long acc[4][2];
    #pragma unroll
    for (int i = 0; i < 4; ++i) { acc[i][0] = 0ull; acc[i][1] = 0ull; }

    const float* arow  = As + (ty * 4) * 256;
    const float* bbase = Bs + tx * 4;

    #pragma unroll 8
    for (int k = 0; k < 256; ++k) {
        unsigned long long a2[4];
        #pragma unroll
        for (int i = 0; i < 4; ++i) {
            const float a = arow[i * 256 + k];   // broadcast LDS
            a2[i] = pack2(a, a);
        }
        const longlong2 bl = *reinterpret_cast<const longlong2*>(bbase + k * 128);
        const unsigned long long bv0 = (unsigned long long)bl.x;
        const unsigned long long bv1 = (unsigned long long)bl.y;
        #pragma unroll
        for (int i = 0; i < 4; ++i) {
            ffma2(acc[i][0], a2[i], bv0);
            ffma2(acc[i][1], a2[i], bv1);
        }
    }

    // LN epilogue over D=128
    const int d0 = tx * 4;
    float b2v[4], g2v[4], be2v[4];
    #pragma unroll
    for (int c = 0; c < 4; ++c) {
        b2v[c] = b2[d0 + c]; g2v[c] = g2[d0 + c]; be2v[c] = be2[d0 + c];
    }
    #pragma unroll
    for (int i = 0; i < 4; ++i) {
        float v[4];
        #pragma unroll
        for (int j = 0; j < 2; ++j) {
            const float2 f = unpack2(acc[i][j]);
            v[2 * j]     = f.x + b2v[2 * j];
            v[2 * j + 1] = f.y + b2v[2 * j + 1];
        }
        float s1 = 0.f, s2 = 0.f;
        #pragma unroll
        for (int c = 0; c < 4; ++c) { s1 += v[c]; s2 += v[c] * v[c]; }
        #pragma unroll
        for (int o = 16; o > 0; o >>= 1) {
            s1 += __shfl_xor_sync(0xffffffffu, s1, o);
            s2 += __shfl_xor_sync(0xffffffffu, s2, o);
        }
        const float m   = s1 * (1.0f / 128.0f);
        const float var = s2 * (1.0f / 128.0f) - m * m;
        const float inv = rsqrtf(var + 1e-5f);
        float ov[4];
        #pragma unroll
        for (int c = 0; c < 4; ++c) ov[c] = (v[c] - m) * inv * g2v[c] + be2v[c];
        const int row = row0 + ty * 4 + i;
        *reinterpret_cast<float4*>(g_o + (size_t)row * D_ + d0) =
            make_float4(ov[0], ov[1], ov[2], ov[3]);
    }
}

// =====================================================================
// Kernel 4: LIF scan layer 2 + residual add: out = x + spike2
// =====================================================================
__global__ void lif2_res_kernel(const float* __restrict__ x, float* __restrict__ out)
{
    const int b = blockIdx.x;
    const int d = threadIdx.x;            // 0..127
    const size_t base = (size_t)b * T_ * D_ + d;
    float v = 0.f;
    #pragma unroll 4
    for (int t = 0; t < T_; ++t) {
        const size_t idx = base + (size_t)t * D_;
        const float ov = g_o[idx];
        const float hm = v + (ov - v) * 0.5f;
        const bool  s  = (hm >= 1.0f);
        v = s ? 0.0f : hm;
        out[idx] = x[idx] + (s ? 1.0f : 0.0f);
    }
}

// =====================================================================
extern "C" void kernel_launch(void* const* d_in, const int* in_sizes, int n_in,
                              void* d_out, int out_size)
{
    const float* x   = (const float*)d_in[0];
    const float* W1  = (const float*)d_in[1];
    const float* b1  = (const float*)d_in[2];
    const float* g1  = (const float*)d_in[3];
    const float* be1 = (const float*)d_in[4];
    const float* W2  = (const float*)d_in[5];
    const float* b2  = (const float*)d_in[6];
    const float* g2  = (const float*)d_in[7];
    const float* be2 = (const float*)d_in[8];
    float* out = (float*)d_out;

    constexpr int SMEM1 = (128 * 128 + 128 * 256) * (int)sizeof(float);  // 196608
    constexpr int SMEM2 = (64 * 256 + 256 * 128) * (int)sizeof(float);   // 196608

    // One-time attribute config on the (uncaptured) correctness call.
    static const bool _cfg = []() {
        cudaFuncSetAttribute(gemm1_ln_kernel, cudaFuncAttributeMaxDynamicSharedMemorySize, SMEM1);
        cudaFuncSetAttribute(gemm2_ln_kernel, cudaFuncAttributeMaxDynamicSharedMemorySize, SMEM2);
        return true;
    }();
    (void)_cfg; (void)in_sizes; (void)n_in; (void)out_size;

    gemm1_ln_kernel<<<BT_ / 128, 512, SMEM1>>>(x, W1, b1, g1, be1);
    lif1_kernel<<<B_, H_>>>();
    gemm2_ln_kernel<<<BT_ / 64, 512, SMEM2>>>(W2, b2, g2, be2);
    lif2_res_kernel<<<B_, D_>>>(x, out);
}

// round 2
// speedup vs baseline: 1.1424x; 1.1424x over previous
#include <cuda_runtime.h>
#include <cstdint>
#include <cstddef>

#define B_  256
#define T_  256
#define D_  128
#define H_  256
#define BT_ 65536

typedef unsigned long long u64;

// Scratch (allocation-free rule: __device__ globals)
__device__ float g_h [(size_t)BT_ * H_];  // post-LN hidden  [BT,256]
__device__ float g_s1[(size_t)BT_ * H_];  // layer-1 spikes  [BT,256] (exact 0/1)
__device__ float g_o [(size_t)BT_ * D_];  // post-LN output  [BT,128]

// ---------- packed fp32x2 helpers (sm_103a FFMA2 path) ----------
__device__ __forceinline__ u64 pack2(float x, float y) {
    u64 r;
    asm("mov.b64 %0, {%1, %2};" : "=l"(r) : "f"(x), "f"(y));
    return r;
}
__device__ __forceinline__ float2 unpack2(u64 v) {
    float2 f;
    asm("mov.b64 {%0, %1}, %2;" : "=f"(f.x), "=f"(f.y) : "l"(v));
    return f;
}
__device__ __forceinline__ void ffma2(u64& c, u64 a, u64 b) {
    asm("fma.rn.f32x2 %0, %1, %2, %3;" : "=l"(c) : "l"(a), "l"(b), "l"(c));
}

// =====================================================================
// Kernel 1: h_ln = LN_H( x @ W1^T + b1 ) * g1 + be1
// tile 128 rows x 256 cols, K=128 in 2 chunks of 64. 512 threads.
// SMEM: Bs[k][h] 128x256 f32 (128KB) + As2[k][r] 64x128 dup-f32x2 (64KB)
// Warp ty: rows ty*8..+7. Lane tx: cols {tx*4..+3} U {128+tx*4..+3}.
// =====================================================================
__global__ __launch_bounds__(512, 1)
void gemm1_ln_kernel(const float* __restrict__ x, const float* __restrict__ W1,
                     const float* __restrict__ b1, const float* __restrict__ g1,
                     const float* __restrict__ be1)
{
    extern __shared__ float smem[];
    float* Bs = smem;                       // [128][256]
    u64*   As2 = (u64*)(smem + 128 * 256);  // [64][128] dup pairs

    const int tid  = threadIdx.x;
    const int row0 = blockIdx.x * 128;

    // ---- stage W1 transposed -> Bs[k][h] (full K, once) ----
    {
        const int h  = tid >> 1;
        const int q0 = tid & 1;
        #pragma unroll
        for (int p = 0; p < 16; ++p) {
            const int q = p * 2 + q0;  // k-quad 0..31
            float4 v = *reinterpret_cast<const float4*>(W1 + (size_t)h * D_ + q * 4);
            Bs[(q * 4 + 0) * 256 + h] = v.x;
            Bs[(q * 4 + 1) * 256 + h] = v.y;
            Bs[(q * 4 + 2) * 256 + h] = v.z;
            Bs[(q * 4 + 3) * 256 + h] = v.w;
        }
    }

    const int r_st = tid & 127;   // staging row
    const int kk   = tid >> 7;    // staging k-group 0..3
    const int ty   = tid >> 5;    // warp: rows ty*8..+7
    const int tx   = tid & 31;    // lane: col groups

    u64 acc[8][4];
    #pragma unroll
    for (int i = 0; i < 8; ++i)
        #pragma unroll
        for (int j = 0; j < 4; ++j) acc[i][j] = 0ull;

    #pragma unroll
    for (int chunk = 0; chunk < 2; ++chunk) {
        const int kc = chunk * 64;
        if (chunk) __syncthreads();  // previous compute done before restage
        // ---- stage x chunk -> As2[k_local][r] duplicated ----
        #pragma unroll
        for (int p = 0; p < 4; ++p) {
            const int q = kk + p * 4;  // k-quad 0..15 within chunk
            float4 v = *reinterpret_cast<const float4*>(
                x + (size_t)(row0 + r_st) * D_ + kc + q * 4);
            As2[(q * 4 + 0) * 128 + r_st] = pack2(v.x, v.x);
            As2[(q * 4 + 1) * 128 + r_st] = pack2(v.y, v.y);
            As2[(q * 4 + 2) * 128 + r_st] = pack2(v.z, v.z);
            As2[(q * 4 + 3) * 128 + r_st] = pack2(v.w, v.w);
        }
        __syncthreads();

        const float* bb = Bs + kc * 0 + tx * 4;  // col base (kc only offsets k index)
        #pragma unroll 2
        for (int k = 0; k < 64; ++k) {
            // a: 4 x LDS.128 broadcast (2 dup-pairs each)
            const ulonglong2* ap =
                reinterpret_cast<const ulonglong2*>(As2 + k * 128 + ty * 8);
            ulonglong2 a01 = ap[0], a23 = ap[1], a45 = ap[2], a67 = ap[3];
            u64 a2[8] = {a01.x, a01.y, a23.x, a23.y, a45.x, a45.y, a67.x, a67.y};
            // b: 2 x LDS.128 lane-contiguous
            const int kg = kc + k;
            const longlong2 bA = *reinterpret_cast<const longlong2*>(bb + kg * 256);
            const longlong2 bB = *reinterpret_cast<const longlong2*>(bb + kg * 256 + 128);
            const u64 bv[4] = {(u64)bA.x, (u64)bA.y, (u64)bB.x, (u64)bB.y};
            #pragma unroll
            for (int i = 0; i < 8; ++i)
                #pragma unroll
                for (int j = 0; j < 4; ++j) ffma2(acc[i][j], a2[i], bv[j]);
        }
    }

    // ---- LN epilogue (per-row warp allreduce over H=256) ----
    const int c0 = tx * 4;          // cols c0..c0+3 and 128+c0..+3
    float b1a[4], g1a[4], be1a[4], b1b[4], g1b[4], be1b[4];
    #pragma unroll
    for (int c = 0; c < 4; ++c) {
        b1a[c] = b1[c0 + c];       g1a[c] = g1[c0 + c];       be1a[c] = be1[c0 + c];
        b1b[c] = b1[128 + c0 + c]; g1b[c] = g1[128 + c0 + c]; be1b[c] = be1[128 + c0 + c];
    }
    #pragma unroll
    for (int i = 0; i < 8; ++i) {
        float v[8];
        #pragma unroll
        for (int j = 0; j < 2; ++j) {
            float2 fa = unpack2(acc[i][j]);
            v[2 * j]     = fa.x + b1a[2 * j];
            v[2 * j + 1] = fa.y + b1a[2 * j + 1];
            float2 fb = unpack2(acc[i][2 + j]);
            v[4 + 2 * j]     = fb.x + b1b[2 * j];
            v[4 + 2 * j + 1] = fb.y + b1b[2 * j + 1];
        }
        float s1 = 0.f, s2 = 0.f;
        #pragma unroll
        for (int c = 0; c < 8; ++c) { s1 += v[c]; s2 += v[c] * v[c]; }
        #pragma unroll
        for (int o = 16; o > 0; o >>= 1) {
            s1 += __shfl_xor_sync(0xffffffffu, s1, o);
            s2 += __shfl_xor_sync(0xffffffffu, s2, o);
        }
        const float m   = s1 * (1.0f / 256.0f);
        const float var = s2 * (1.0f / 256.0f) - m * m;
        const float inv = rsqrtf(var + 1e-5f);
        float oa[4], ob[4];
        #pragma unroll
        for (int c = 0; c < 4; ++c) {
            oa[c] = (v[c] - m) * inv * g1a[c] + be1a[c];
            ob[c] = (v[4 + c] - m) * inv * g1b[c] + be1b[c];
        }
        const int row = row0 + ty * 8 + i;
        *reinterpret_cast<float4*>(g_h + (size_t)row * H_ + c0) =
            make_float4(oa[0], oa[1], oa[2], oa[3]);
        *reinterpret_cast<float4*>(g_h + (size_t)row * H_ + 128 + c0) =
            make_float4(ob[0], ob[1], ob[2], ob[3]);
    }
}

// =====================================================================
// Kernel 2: LIF scan layer 1 (MLP=16 batched loads)
// =====================================================================
__global__ __launch_bounds__(256)
void lif1_kernel()
{
    const int lane = blockIdx.x * 256 + threadIdx.x;  // 0..65535
    const int b = lane >> 8, h = lane & 255;
    const size_t base = (size_t)b * T_ * H_ + h;
    float v = 0.f;
    for (int t0 = 0; t0 < T_; t0 += 16) {
        float xs[16];
        #pragma unroll
        for (int u = 0; u < 16; ++u) xs[u] = g_h[base + (size_t)(t0 + u) * H_];
        #pragma unroll
        for (int u = 0; u < 16; ++u) {
            const float hm = v + (xs[u] - v) * 0.5f;
            const bool  s  = (hm >= 1.0f);
            xs[u] = s ? 1.0f : 0.0f;
            v = s ? 0.0f : hm;
        }
        #pragma unroll
        for (int u = 0; u < 16; ++u) g_s1[base + (size_t)(t0 + u) * H_] = xs[u];
    }
}

// =====================================================================
// Kernel 3: o_ln = LN_D( s1 @ W2^T + b2 ) * g2 + be2
// tile 128 rows x 128 cols, K=256 in 4 chunks of 64. 256 threads, occ 2.
// SMEM: Bs[k][d] 64x128 f32 (32KB) + As2[k][r] 64x128 dup (64KB) = 96KB
// Warp w: rows w*16..+15. Lane tx: cols tx*4..+3.
// =====================================================================
__global__ __launch_bounds__(256, 2)
void gemm2_ln_kernel(const float* __restrict__ W2, const float* __restrict__ b2,
                     const float* __restrict__ g2, const float* __restrict__ be2)
{
    extern __shared__ float smem[];
    float* Bs = smem;                      // [64][128] per chunk
    u64*   As2 = (u64*)(smem + 64 * 128);  // [64][128] dup pairs

    const int tid  = threadIdx.x;
    const int row0 = blockIdx.x * 128;

    const int r_st = tid & 127;  // staging row
    const int kk   = tid >> 7;   // 0..1
    const int dW   = tid >> 1;   // Bs staging: 0..127
    const int qW0  = tid & 1;
    const int w    = tid >> 5;   // warp: rows w*16..+15
    const int tx   = tid & 31;   // lane: cols tx*4..+3

    u64 acc[16][2];
    #pragma unroll
    for (int i = 0; i < 16; ++i) { acc[i][0] = 0ull; acc[i][1] = 0ull; }

    #pragma unroll
    for (int chunk = 0; chunk < 4; ++chunk) {
        const int kc = chunk * 64;
        if (chunk) __syncthreads();
        // stage spikes -> As2 duplicated
        #pragma unroll
        for (int p = 0; p < 8; ++p) {
            const int q = kk + p * 2;  // k-quad 0..15
            float4 v = *reinterpret_cast<const float4*>(
                g_s1 + (size_t)(row0 + r_st) * H_ + kc + q * 4);
            As2[(q * 4 + 0) * 128 + r_st] = pack2(v.x, v.x);
            As2[(q * 4 + 1) * 128 + r_st] = pack2(v.y, v.y);
            As2[(q * 4 + 2) * 128 + r_st] = pack2(v.z, v.z);
            As2[(q * 4 + 3) * 128 + r_st] = pack2(v.w, v.w);
        }
        // stage W2 chunk transposed -> Bs[k][d]
        #pragma unroll
        for (int p = 0; p < 8; ++p) {
            const int q = p * 2 + qW0;  // k-quad 0..15
            float4 v = *reinterpret_cast<const float4*>(
                W2 + (size_t)dW * H_ + kc + q * 4);
            Bs[(q * 4 + 0) * 128 + dW] = v.x;
            Bs[(q * 4 + 1) * 128 + dW] = v.y;
            Bs[(q * 4 + 2) * 128 + dW] = v.z;
            Bs[(q * 4 + 3) * 128 + dW] = v.w;
        }
        __syncthreads();

        const float* bb = Bs + tx * 4;
        #pragma unroll 2
        for (int k = 0; k < 64; ++k) {
            const ulonglong2* ap =
                reinterpret_cast<const ulonglong2*>(As2 + k * 128 + w * 16);
            u64 a2[16];
            #pragma unroll
            for (int ii = 0; ii < 8; ++ii) {
                ulonglong2 aa = ap[ii];
                a2[2 * ii] = aa.x; a2[2 * ii + 1] = aa.y;
            }
            const longlong2 bl = *reinterpret_cast<const longlong2*>(bb + k * 128);
            const u64 bv0 = (u64)bl.x, bv1 = (u64)bl.y;
            #pragma unroll
            for (int i = 0; i < 16; ++i) {
                ffma2(acc[i][0], a2[i], bv0);
                ffma2(acc[i][1], a2[i], bv1);
            }
        }
    }

    // ---- LN epilogue over D=128 ----
    const int d0 = tx * 4;
    float b2v[4], g2v[4], be2v[4];
    #pragma unroll
    for (int c = 0; c < 4; ++c) {
        b2v[c] = b2[d0 + c]; g2v[c] = g2[d0 + c]; be2v[c] = be2[d0 + c];
    }
    #pragma unroll
    for (int i = 0; i < 16; ++i) {
        float v[4];
        #pragma unroll
        for (int j = 0; j < 2; ++j) {
            const float2 f = unpack2(acc[i][j]);
            v[2 * j]     = f.x + b2v[2 * j];
            v[2 * j + 1] = f.y + b2v[2 * j + 1];
        }
        float s1 = 0.f, s2 = 0.f;
        #pragma unroll
        for (int c = 0; c < 4; ++c) { s1 += v[c]; s2 += v[c] * v[c]; }
        #pragma unroll
        for (int o = 16; o > 0; o >>= 1) {
            s1 += __shfl_xor_sync(0xffffffffu, s1, o);
            s2 += __shfl_xor_sync(0xffffffffu, s2, o);
        }
        const float m   = s1 * (1.0f / 128.0f);
        const float var = s2 * (1.0f / 128.0f) - m * m;
        const float inv = rsqrtf(var + 1e-5f);
        float ov[4];
        #pragma unroll
        for (int c = 0; c < 4; ++c) ov[c] = (v[c] - m) * inv * g2v[c] + be2v[c];
        const int row = row0 + w * 16 + i;
        *reinterpret_cast<float4*>(g_o + (size_t)row * D_ + d0) =
            make_float4(ov[0], ov[1], ov[2], ov[3]);
    }
}

// =====================================================================
// Kernel 4: LIF scan layer 2 + residual (MLP=16)
// =====================================================================
__global__ __launch_bounds__(256)
void lif2_res_kernel(const float* __restrict__ x, float* __restrict__ out)
{
    const int lane = blockIdx.x * 256 + threadIdx.x;  // 0..32767
    const int b = lane >> 7, d = lane & 127;
    const size_t base = (size_t)b * T_ * D_ + d;
    float v = 0.f;
    for (int t0 = 0; t0 < T_; t0 += 16) {
        float os[16], xr[16];
        #pragma unroll
        for (int u = 0; u < 16; ++u) {
            const size_t idx = base + (size_t)(t0 + u) * D_;
            os[u] = g_o[idx];
            xr[u] = x[idx];
        }
        #pragma unroll
        for (int u = 0; u < 16; ++u) {
            const float hm = v + (os[u] - v) * 0.5f;
            const bool  s  = (hm >= 1.0f);
            v = s ? 0.0f : hm;
            os[u] = xr[u] + (s ? 1.0f : 0.0f);
        }
        #pragma unroll
        for (int u = 0; u < 16; ++u)
            out[base + (size_t)(t0 + u) * D_] = os[u];
    }
}

// =====================================================================
extern "C" void kernel_launch(void* const* d_in, const int* in_sizes, int n_in,
                              void* d_out, int out_size)
{
    const float* x   = (const float*)d_in[0];
    const float* W1  = (const float*)d_in[1];
    const float* b1  = (const float*)d_in[2];
    const float* g1  = (const float*)d_in[3];
    const float* be1 = (const float*)d_in[4];
    const float* W2  = (const float*)d_in[5];
    const float* b2  = (const float*)d_in[6];
    const float* g2  = (const float*)d_in[7];
    const float* be2 = (const float*)d_in[8];
    float* out = (float*)d_out;

    constexpr int SMEM1 = 128 * 256 * 4 + 64 * 128 * 8;  // 128KB + 64KB = 196608
    constexpr int SMEM2 = 64 * 128 * 4 + 64 * 128 * 8;   // 32KB + 64KB  = 98304

    static const bool _cfg = []() {
        cudaFuncSetAttribute(gemm1_ln_kernel, cudaFuncAttributeMaxDynamicSharedMemorySize, SMEM1);
        cudaFuncSetAttribute(gemm2_ln_kernel, cudaFuncAttributeMaxDynamicSharedMemorySize, SMEM2);
        return true;
    }();
    (void)_cfg; (void)in_sizes; (void)n_in; (void)out_size;

    gemm1_ln_kernel<<<BT_ / 128, 512, SMEM1>>>(x, W1, b1, g1, be1);
    lif1_kernel<<<B_, 256>>>();
    gemm2_ln_kernel<<<BT_ / 128, 256, SMEM2>>>(W2, b2, g2, be2);
    lif2_res_kernel<<<BT_ * D_ / T_ / 256 / 128 * 128, 256>>>(x, out);
}

// round 4
// speedup vs baseline: 3.1141x; 2.7259x over previous
#include <cuda_runtime.h>
#include <cuda_fp16.h>
#include <cstdint>
#include <cstddef>

#define B_  256
#define T_  256
#define D_  128
#define H_  256
#define BT_ 65536

// ---------------- global scratch ----------------
__device__ float  g_h [(size_t)BT_ * H_];   // post-LN hidden  [BT,256] fp32
__device__ __half g_s1[(size_t)BT_ * H_];   // layer-1 spikes  [BT,256] fp16 exact {0,1}
__device__ float  g_o [(size_t)BT_ * D_];   // post-LN output  [BT,128] fp32
// padded fp16 weight images ready for direct SMEM copy
// W1: [256][136] halves  (K=128 + 8 pad),  W2: [128][264] halves (K=256 + 8 pad)
__device__ __align__(16) __half g_W1h[256 * 136];
__device__ __align__(16) __half g_W1l[256 * 136];
__device__ __align__(16) __half g_W2h[128 * 264];
__device__ __align__(16) __half g_W2l[128 * 264];

// ---------------- helpers ----------------
__device__ __forceinline__ uint32_t smem_u32(const void* p) {
    uint32_t a;
    asm("{ .reg .u64 t; cvta.to.shared.u64 t, %1; cvt.u32.u64 %0, t; }" : "=r"(a) : "l"(p));
    return a;
}
#define CP16(dst, src) asm volatile("cp.async.cg.shared.global [%0], [%1], 16;" :: "r"(dst), "l"(src))
#define CP_COMMIT()    asm volatile("cp.async.commit_group;" ::: "memory")
#define CP_WAIT0()     asm volatile("cp.async.wait_group 0;" ::: "memory")
#define CP_WAIT1()     asm volatile("cp.async.wait_group 1;" ::: "memory")

__device__ __forceinline__ void ldsm4(uint32_t* r, uint32_t addr) {
    asm volatile("ldmatrix.sync.aligned.m8n8.x4.shared.b16 {%0,%1,%2,%3}, [%4];"
                 : "=r"(r[0]), "=r"(r[1]), "=r"(r[2]), "=r"(r[3]) : "r"(addr));
}
__device__ __forceinline__ void mma16816(float* d, const uint32_t* a, const uint32_t* b) {
    asm volatile("mma.sync.aligned.m16n8k16.row.col.f32.f16.f16.f32 "
                 "{%0,%1,%2,%3}, {%4,%5,%6,%7}, {%8,%9}, {%0,%1,%2,%3};"
                 : "+f"(d[0]), "+f"(d[1]), "+f"(d[2]), "+f"(d[3])
                 : "r"(a[0]), "r"(a[1]), "r"(a[2]), "r"(a[3]), "r"(b[0]), "r"(b[1]));
}
__device__ __forceinline__ void split2(float f, __half& hi, __half& lo) {
    hi = __float2half_rn(f);
    lo = __float2half_rn(f - __half2float(hi));
}

// =====================================================================
// Prep: split W1/W2 into fp16 hi/lo padded images
// =====================================================================
__global__ void prep_kernel(const float* __restrict__ W1, const float* __restrict__ W2)
{
    const int idx = blockIdx.x * blockDim.x + threadIdx.x;  // 0..32767
    {
        const int n = idx >> 7, k = idx & 127;
        __half hi, lo; split2(W1[idx], hi, lo);
        g_W1h[n * 136 + k] = hi;
        g_W1l[n * 136 + k] = lo;
    }
    {
        const int n = idx >> 8, k = idx & 255;
        __half hi, lo; split2(W2[idx], hi, lo);
        g_W2h[n * 264 + k] = hi;
        g_W2l[n * 264 + k] = lo;
    }
}

// =====================================================================
// GEMM1 + LN : g_h = LN_256( x @ W1^T + b1 ) * g1 + be1
// block: 512 thr (16 warps), tile M=128, N=256, K=128, 3 split passes.
// warp (wm=wid>>2, wn=wid&3): rows wm*32..+31, cols wn*64..+63.
// =====================================================================
#define PK1  136
#define RB1  272
#define G1_AH   0
#define G1_AL   34816
#define G1_BH   69632
#define G1_BL   139264
#define G1_PB   208896
#define G1_PG   209920
#define G1_PE   210944
#define G1_RED  211968
#define G1_MI   216064
#define G1_SMEM 217088

__global__ __launch_bounds__(512, 1)
void gemm1_ln_kernel(const float* __restrict__ x, const float* __restrict__ b1,
                     const float* __restrict__ g1, const float* __restrict__ be1)
{
    extern __shared__ char smem[];
    const uint32_t sb = smem_u32(smem);
    const int tid = threadIdx.x;
    const int row0 = blockIdx.x * 128;

    // --- stage B images via cp.async (69632 B each = 4352 x 16B) ---
    for (int i = tid; i < 4352; i += 512) {
        CP16(sb + G1_BH + (uint32_t)i * 16u, (const char*)g_W1h + (size_t)i * 16);
        CP16(sb + G1_BL + (uint32_t)i * 16u, (const char*)g_W1l + (size_t)i * 16);
    }
    CP_COMMIT();

    // --- stage A: load x fp32, split hi/lo, store padded ---
    {
        const int r = tid >> 2, q = (tid & 3) * 32;
        const float4* xs = (const float4*)(x + (size_t)(row0 + r) * 128 + q);
        __half* pH = (__half*)(smem + G1_AH) + r * PK1 + q;
        __half* pL = (__half*)(smem + G1_AL) + r * PK1 + q;
        #pragma unroll
        for (int i = 0; i < 8; ++i) {
            float4 f = xs[i];
            __half h0, h1, h2, h3, l0, l1, l2, l3;
            split2(f.x, h0, l0); split2(f.y, h1, l1);
            split2(f.z, h2, l2); split2(f.w, h3, l3);
            *(__half2*)(pH + i * 4)     = __halves2half2(h0, h1);
            *(__half2*)(pH + i * 4 + 2) = __halves2half2(h2, h3);
            *(__half2*)(pL + i * 4)     = __halves2half2(l0, l1);
            *(__half2*)(pL + i * 4 + 2) = __halves2half2(l2, l3);
        }
    }
    if (tid < 256) {
        ((float*)(smem + G1_PB))[tid] = b1[tid];
        ((float*)(smem + G1_PG))[tid] = g1[tid];
        ((float*)(smem + G1_PE))[tid] = be1[tid];
    }
    CP_WAIT0();
    __syncthreads();

    // --- compute ---
    const int wid = tid >> 5, lane = tid & 31;
    const int wm = wid >> 2, wn = wid & 3;
    const int grp = lane >> 3, l7 = lane & 7;

    uint32_t aAh[2], aAl[2], aBh[4], aBl[4];
    #pragma unroll
    for (int mi = 0; mi < 2; ++mi) {
        const int rm = wm * 32 + mi * 16 + (grp & 1) * 8 + l7;
        aAh[mi] = sb + G1_AH + (uint32_t)rm * RB1 + (grp >> 1) * 16;
        aAl[mi] = sb + G1_AL + (uint32_t)rm * RB1 + (grp >> 1) * 16;
    }
    #pragma unroll
    for (int p = 0; p < 4; ++p) {
        const int rn = wn * 64 + p * 16 + (grp >> 1) * 8 + l7;
        aBh[p] = sb + G1_BH + (uint32_t)rn * RB1 + (grp & 1) * 16;
        aBl[p] = sb + G1_BL + (uint32_t)rn * RB1 + (grp & 1) * 16;
    }

    float acc[2][8][4];
    #pragma unroll
    for (int i = 0; i < 2; ++i)
        #pragma unroll
        for (int j = 0; j < 8; ++j)
            #pragma unroll
            for (int c = 0; c < 4; ++c) acc[i][j][c] = 0.f;

    #pragma unroll
    for (int s = 0; s < 8; ++s) {
        const uint32_t kb = (uint32_t)s * 32u;
        uint32_t ah0[4], ah1[4], al0[4], al1[4];
        ldsm4(ah0, aAh[0] + kb); ldsm4(ah1, aAh[1] + kb);
        ldsm4(al0, aAl[0] + kb); ldsm4(al1, aAl[1] + kb);
        #pragma unroll
        for (int p = 0; p < 4; ++p) {
            uint32_t tb[4], tl[4];
            ldsm4(tb, aBh[p] + kb);
            ldsm4(tl, aBl[p] + kb);
            mma16816(acc[0][2 * p], ah0, tb);     mma16816(acc[1][2 * p], ah1, tb);
            mma16816(acc[0][2 * p], ah0, tl);     mma16816(acc[1][2 * p], ah1, tl);
            mma16816(acc[0][2 * p], al0, tb);     mma16816(acc[1][2 * p], al1, tb);
            mma16816(acc[0][2 * p + 1], ah0, tb + 2); mma16816(acc[1][2 * p + 1], ah1, tb + 2);
            mma16816(acc[0][2 * p + 1], ah0, tl + 2); mma16816(acc[1][2 * p + 1], ah1, tl + 2);
            mma16816(acc[0][2 * p + 1], al0, tb + 2); mma16816(acc[1][2 * p + 1], al1, tb + 2);
        }
    }

    // --- LN epilogue ---
    const float* sB = (const float*)(smem + G1_PB);
    const float* sG = (const float*)(smem + G1_PG);
    const float* sE = (const float*)(smem + G1_PE);
    float* RED = (float*)(smem + G1_RED);
    float* MI  = (float*)(smem + G1_MI);
    const int r4 = lane >> 2, cq = (lane & 3) * 2;

    #pragma unroll
    for (int mi = 0; mi < 2; ++mi)
        #pragma unroll
        for (int h = 0; h < 2; ++h) {
            const int rl = wm * 32 + mi * 16 + h * 8 + r4;
            float s = 0.f, sq = 0.f;
            #pragma unroll
            for (int ni = 0; ni < 8; ++ni) {
                const int c = wn * 64 + ni * 8 + cq;
                const float v0 = acc[mi][ni][2 * h] + sB[c];
                const float v1 = acc[mi][ni][2 * h + 1] + sB[c + 1];
                s += v0 + v1; sq += v0 * v0 + v1 * v1;
            }
            s  += __shfl_xor_sync(0xffffffffu, s, 1);
            sq += __shfl_xor_sync(0xffffffffu, sq, 1);
            s  += __shfl_xor_sync(0xffffffffu, s, 2);
            sq += __shfl_xor_sync(0xffffffffu, sq, 2);
            if ((lane & 3) == 0) {
                RED[rl * 8 + wn * 2]     = s;
                RED[rl * 8 + wn * 2 + 1] = sq;
            }
        }
    __syncthreads();
    if (tid < 128) {
        float s = 0.f, sq = 0.f;
        #pragma unroll
        for (int w = 0; w < 4; ++w) { s += RED[tid * 8 + w * 2]; sq += RED[tid * 8 + w * 2 + 1]; }
        const float m   = s * (1.0f / 256.0f);
        const float var = sq * (1.0f / 256.0f) - m * m;
        MI[tid * 2]     = m;
        MI[tid * 2 + 1] = rsqrtf(var + 1e-5f);
    }
    __syncthreads();
    #pragma unroll
    for (int mi = 0; mi < 2; ++mi)
        #pragma unroll
        for (int h = 0; h < 2; ++h) {
            const int rl = wm * 32 + mi * 16 + h * 8 + r4;
            const float m = MI[rl * 2], inv = MI[rl * 2 + 1];
            float* dst = g_h + (size_t)(row0 + rl) * 256;
            #pragma unroll
            for (int ni = 0; ni < 8; ++ni) {
                const int c = wn * 64 + ni * 8 + cq;
                const float v0 = acc[mi][ni][2 * h] + sB[c];
                const float v1 = acc[mi][ni][2 * h + 1] + sB[c + 1];
                float2 o;
                o.x = (v0 - m) * inv * sG[c] + sE[c];
                o.y = (v1 - m) * inv * sG[c + 1] + sE[c + 1];
                *(float2*)(dst + c) = o;
            }
        }
}

// =====================================================================
// LIF1: sequential scan over T; cp.async double-buffered 64-t chunks.
// =====================================================================
__global__ __launch_bounds__(256, 1)
void lif1_kernel()
{
    extern __shared__ float sm[];  // 2 x 16384 f32
    const int b = blockIdx.x, tid = threadIdx.x;
    const size_t base = (size_t)b * T_ * H_;
    const uint32_t sb = smem_u32(sm);

    auto prefetch = [&](int c) {
        const float* src = g_h + base + (size_t)c * 64 * H_;
        const uint32_t dst = sb + (uint32_t)(c & 1) * 65536u;
        #pragma unroll
        for (int i = 0; i < 16; ++i) {
            const int u = i * 256 + tid;
            CP16(dst + (uint32_t)u * 16u, src + (size_t)u * 4);
        }
    };
    prefetch(0); CP_COMMIT();
    float v = 0.f;
    for (int c = 0; c < 4; ++c) {
        if (c < 3) { prefetch(c + 1); CP_COMMIT(); CP_WAIT1(); }
        else       { CP_WAIT0(); }
        __syncthreads();
        const float* buf = sm + (c & 1) * 16384;
        __half* dst = g_s1 + base + (size_t)c * 64 * H_ + tid;
        #pragma unroll 8
        for (int t = 0; t < 64; ++t) {
            const float xv = buf[t * 256 + tid];
            const float hm = v + (xv - v) * 0.5f;
            const bool  s  = (hm >= 1.0f);
            dst[(size_t)t * H_] = s ? __float2half(1.0f) : __float2half(0.0f);
            v = s ? 0.f : hm;
        }
        __syncthreads();
    }
}

// =====================================================================
// GEMM2 + LN : g_o = LN_128( s1 @ W2^T + b2 ) * g2 + be2
// block: 512 thr, tile M=128, N=128, K=256, 2 passes (A exact fp16).
// warp (wm, wn): rows wm*32..+31, cols wn*32..+31.
// =====================================================================
#define PK2  264
#define RB2  528
#define G2_AS   0
#define G2_BH   67584
#define G2_BL   135168
#define G2_PB   202752
#define G2_PG   203264
#define G2_PE   203776
#define G2_RED  204288
#define G2_MI   208384
#define G2_SMEM 209408

__global__ __launch_bounds__(512, 1)
void gemm2_ln_kernel(const float* __restrict__ b2, const float* __restrict__ g2,
                     const float* __restrict__ be2)
{
    extern __shared__ char smem[];
    const uint32_t sb = smem_u32(smem);
    const int tid = threadIdx.x;
    const int row0 = blockIdx.x * 128;

    // stage A (spikes, fp16): 128 rows x 32 chunks of 16B
    for (int i = tid; i < 4096; i += 512) {
        const int r = i >> 5, c = i & 31;
        CP16(sb + G2_AS + (uint32_t)(r * RB2 + c * 16),
             g_s1 + (size_t)(row0 + r) * 256 + c * 8);
    }
    // stage B images: 67584 B = 4224 x 16B each
    for (int i = tid; i < 4224; i += 512) {
        CP16(sb + G2_BH + (uint32_t)i * 16u, (const char*)g_W2h + (size_t)i * 16);
        CP16(sb + G2_BL + (uint32_t)i * 16u, (const char*)g_W2l + (size_t)i * 16);
    }
    CP_COMMIT();
    if (tid < 128) {
        ((float*)(smem + G2_PB))[tid] = b2[tid];
        ((float*)(smem + G2_PG))[tid] = g2[tid];
        ((float*)(smem + G2_PE))[tid] = be2[tid];
    }
    CP_WAIT0();
    __syncthreads();

    const int wid = tid >> 5, lane = tid & 31;
    const int wm = wid >> 2, wn = wid & 3;
    const int grp = lane >> 3, l7 = lane & 7;

    uint32_t aA[2], aBh[2], aBl[2];
    #pragma unroll
    for (int mi = 0; mi < 2; ++mi) {
        const int rm = wm * 32 + mi * 16 + (grp & 1) * 8 + l7;
        aA[mi] = sb + G2_AS + (uint32_t)rm * RB2 + (grp >> 1) * 16;
    }
    #pragma unroll
    for (int p = 0; p < 2; ++p) {
        const int rn = wn * 32 + p * 16 + (grp >> 1) * 8 + l7;
        aBh[p] = sb + G2_BH + (uint32_t)rn * RB2 + (grp & 1) * 16;
        aBl[p] = sb + G2_BL + (uint32_t)rn * RB2 + (grp & 1) * 16;
    }

    float acc[2][4][4];
    #pragma unroll
    for (int i = 0; i < 2; ++i)
        #pragma unroll
        for (int j = 0; j < 4; ++j)
            #pragma unroll
            for (int c = 0; c < 4; ++c) acc[i][j][c] = 0.f;

    #pragma unroll
    for (int s = 0; s < 16; ++s) {
        const uint32_t kb = (uint32_t)s * 32u;
        uint32_t a0[4], a1[4];
        ldsm4(a0, aA[0] + kb); ldsm4(a1, aA[1] + kb);
        #pragma unroll
        for (int p = 0; p < 2; ++p) {
            uint32_t tb[4], tl[4];
            ldsm4(tb, aBh[p] + kb);
            ldsm4(tl, aBl[p] + kb);
            mma16816(acc[0][2 * p], a0, tb);     mma16816(acc[1][2 * p], a1, tb);
            mma16816(acc[0][2 * p], a0, tl);     mma16816(acc[1][2 * p], a1, tl);
            mma16816(acc[0][2 * p + 1], a0, tb + 2); mma16816(acc[1][2 * p + 1], a1, tb + 2);
            mma16816(acc[0][2 * p + 1], a0, tl + 2); mma16816(acc[1][2 * p + 1], a1, tl + 2);
        }
    }

    // --- LN epilogue over D=128 ---
    const float* sB = (const float*)(smem + G2_PB);
    const float* sG = (const float*)(smem + G2_PG);
    const float* sE = (const float*)(smem + G2_PE);
    float* RED = (float*)(smem + G2_RED);
    float* MI  = (float*)(smem + G2_MI);
    const int r4 = lane >> 2, cq = (lane & 3) * 2;

    #pragma unroll
    for (int mi = 0; mi < 2; ++mi)
        #pragma unroll
        for (int h = 0; h < 2; ++h) {
            const int rl = wm * 32 + mi * 16 + h * 8 + r4;
            float s = 0.f, sq = 0.f;
            #pragma unroll
            for (int ni = 0; ni < 4; ++ni) {
                const int c = wn * 32 + ni * 8 + cq;
                const float v0 = acc[mi][ni][2 * h] + sB[c];
                const float v1 = acc[mi][ni][2 * h + 1] + sB[c + 1];
                s += v0 + v1; sq += v0 * v0 + v1 * v1;
            }
            s  += __shfl_xor_sync(0xffffffffu, s, 1);
            sq += __shfl_xor_sync(0xffffffffu, sq, 1);
            s  += __shfl_xor_sync(0xffffffffu, s, 2);
            sq += __shfl_xor_sync(0xffffffffu, sq, 2);
            if ((lane & 3) == 0) {
                RED[rl * 8 + wn * 2]     = s;
                RED[rl * 8 + wn * 2 + 1] = sq;
            }
        }
    __syncthreads();
    if (tid < 128) {
        float s = 0.f, sq = 0.f;
        #pragma unroll
        for (int w = 0; w < 4; ++w) { s += RED[tid * 8 + w * 2]; sq += RED[tid * 8 + w * 2 + 1]; }
        const float m   = s * (1.0f / 128.0f);
        const float var = sq * (1.0f / 128.0f) - m * m;
        MI[tid * 2]     = m;
        MI[tid * 2 + 1] = rsqrtf(var + 1e-5f);
    }
    __syncthreads();
    #pragma unroll
    for (int mi = 0; mi < 2; ++mi)
        #pragma unroll
        for (int h = 0; h < 2; ++h) {
            const int rl = wm * 32 + mi * 16 + h * 8 + r4;
            const float m = MI[rl * 2], inv = MI[rl * 2 + 1];
            float* dst = g_o + (size_t)(row0 + rl) * 128;
            #pragma unroll
            for (int ni = 0; ni < 4; ++ni) {
                const int c = wn * 32 + ni * 8 + cq;
                const float v0 = acc[mi][ni][2 * h] + sB[c];
                const float v1 = acc[mi][ni][2 * h + 1] + sB[c + 1];
                float2 o;
                o.x = (v0 - m) * inv * sG[c] + sE[c];
                o.y = (v1 - m) * inv * sG[c + 1] + sE[c + 1];
                *(float2*)(dst + c) = o;
            }
        }
}

// =====================================================================
// LIF2 + residual: out = x + spike2. cp.async double-buffered.
// =====================================================================
__global__ __launch_bounds__(128, 1)
void lif2_res_kernel(const float* __restrict__ x, float* __restrict__ out)
{
    extern __shared__ float sm[];  // 2 x (8192 + 8192) f32
    const int b = blockIdx.x, tid = threadIdx.x;
    const size_t base = (size_t)b * T_ * D_;
    const uint32_t sb = smem_u32(sm);

    auto prefetch = [&](int c) {
        const float* so = g_o + base + (size_t)c * 64 * D_;
        const float* sx = x   + base + (size_t)c * 64 * D_;
        const uint32_t d0 = sb + (uint32_t)(c & 1) * 65536u;
        #pragma unroll
        for (int i = 0; i < 16; ++i) {
            const int u = i * 128 + tid;
            CP16(d0 + (uint32_t)u * 16u, so + (size_t)u * 4);
            CP16(d0 + 32768u + (uint32_t)u * 16u, sx + (size_t)u * 4);
        }
    };
    prefetch(0); CP_COMMIT();
    float v = 0.f;
    for (int c = 0; c < 4; ++c) {
        if (c < 3) { prefetch(c + 1); CP_COMMIT(); CP_WAIT1(); }
        else       { CP_WAIT0(); }
        __syncthreads();
        const float* bo = sm + (c & 1) * 16384;
        const float* bx = bo + 8192;
        float* dst = out + base + (size_t)c * 64 * D_ + tid;
        #pragma unroll 8
        for (int t = 0; t < 64; ++t) {
            const float ov = bo[t * 128 + tid];
            const float hm = v + (ov - v) * 0.5f;
            const bool  s  = (hm >= 1.0f);
            v = s ? 0.f : hm;
            dst[(size_t)t * D_] = bx[t * 128 + tid] + (s ? 1.0f : 0.0f);
        }
        __syncthreads();
    }
}

// =====================================================================
extern "C" void kernel_launch(void* const* d_in, const int* in_sizes, int n_in,
                              void* d_out, int out_size)
{
    const float* x   = (const float*)d_in[0];
    const float* W1  = (const float*)d_in[1];
    const float* b1  = (const float*)d_in[2];
    const float* g1  = (const float*)d_in[3];
    const float* be1 = (const float*)d_in[4];
    const float* W2  = (const float*)d_in[5];
    const float* b2  = (const float*)d_in[6];
    const float* g2  = (const float*)d_in[7];
    const float* be2 = (const float*)d_in[8];
    float* out = (float*)d_out;

    static const bool _cfg = []() {
        cudaFuncSetAttribute(gemm1_ln_kernel, cudaFuncAttributeMaxDynamicSharedMemorySize, G1_SMEM);
        cudaFuncSetAttribute(gemm2_ln_kernel, cudaFuncAttributeMaxDynamicSharedMemorySize, G2_SMEM);
        cudaFuncSetAttribute(lif1_kernel,     cudaFuncAttributeMaxDynamicSharedMemorySize, 131072);
        cudaFuncSetAttribute(lif2_res_kernel, cudaFuncAttributeMaxDynamicSharedMemorySize, 131072);
        return true;
    }();
    (void)_cfg; (void)in_sizes; (void)n_in; (void)out_size;

    prep_kernel<<<128, 256>>>(W1, W2);
    gemm1_ln_kernel<<<BT_ / 128, 512, G1_SMEM>>>(x, b1, g1, be1);
    lif1_kernel<<<B_, 256, 131072>>>();
    gemm2_ln_kernel<<<BT_ / 128, 512, G2_SMEM>>>(b2, g2, be2);
    lif2_res_kernel<<<B_, 128, 131072>>>(x, out);
}

// round 5
// speedup vs baseline: 3.1255x; 1.0037x over previous
#include <cuda_runtime.h>
#include <cuda_fp16.h>
#include <cstdint>
#include <cstddef>

#define B_  256
#define T_  256
#define D_  128
#define H_  256
#define BT_ 65536

// ---------------- global scratch ----------------
__device__ float  g_h [(size_t)BT_ * H_];   // post-LN hidden  [BT,256] fp32
__device__ __half g_s1[(size_t)BT_ * H_];   // layer-1 spikes  [BT,256] fp16 exact {0,1}
__device__ float  g_o [(size_t)BT_ * D_];   // post-LN output  [BT,128] fp32
// padded fp16 weight images ready for direct SMEM copy
__device__ __align__(16) __half g_W1h[256 * 136];
__device__ __align__(16) __half g_W1l[256 * 136];
__device__ __align__(16) __half g_W2h[128 * 264];
__device__ __align__(16) __half g_W2l[128 * 264];

// ---------------- helpers ----------------
__device__ __forceinline__ uint32_t smem_u32(const void* p) {
    uint32_t a;
    asm("{ .reg .u64 t; cvta.to.shared.u64 t, %1; cvt.u32.u64 %0, t; }" : "=r"(a) : "l"(p));
    return a;
}
#define CP16(dst, src) asm volatile("cp.async.cg.shared.global [%0], [%1], 16;" :: "r"(dst), "l"(src))
#define CP_COMMIT()    asm volatile("cp.async.commit_group;" ::: "memory")
#define CP_WAIT0()     asm volatile("cp.async.wait_group 0;" ::: "memory")
#define CP_WAIT1()     asm volatile("cp.async.wait_group 1;" ::: "memory")

__device__ __forceinline__ void ldsm4(uint32_t* r, uint32_t addr) {
    asm volatile("ldmatrix.sync.aligned.m8n8.x4.shared.b16 {%0,%1,%2,%3}, [%4];"
                 : "=r"(r[0]), "=r"(r[1]), "=r"(r[2]), "=r"(r[3]) : "r"(addr));
}
__device__ __forceinline__ void mma16816(float* d, const uint32_t* a, const uint32_t* b) {
    asm volatile("mma.sync.aligned.m16n8k16.row.col.f32.f16.f16.f32 "
                 "{%0,%1,%2,%3}, {%4,%5,%6,%7}, {%8,%9}, {%0,%1,%2,%3};"
                 : "+f"(d[0]), "+f"(d[1]), "+f"(d[2]), "+f"(d[3])
                 : "r"(a[0]), "r"(a[1]), "r"(a[2]), "r"(a[3]), "r"(b[0]), "r"(b[1]));
}
__device__ __forceinline__ void split2(float f, __half& hi, __half& lo) {
    hi = __float2half_rn(f);
    lo = __float2half_rn(f - __half2float(hi));
}

// =====================================================================
// Prep: split W1/W2 into fp16 hi/lo padded images
// =====================================================================
__global__ void prep_kernel(const float* __restrict__ W1, const float* __restrict__ W2)
{
    const int idx = blockIdx.x * blockDim.x + threadIdx.x;  // 0..32767
    {
        const int n = idx >> 7, k = idx & 127;
        __half hi, lo; split2(W1[idx], hi, lo);
        g_W1h[n * 136 + k] = hi;
        g_W1l[n * 136 + k] = lo;
    }
    {
        const int n = idx >> 8, k = idx & 255;
        __half hi, lo; split2(W2[idx], hi, lo);
        g_W2h[n * 264 + k] = hi;
        g_W2l[n * 264 + k] = lo;
    }
}

// =====================================================================
// GEMM1 + LN : g_h = LN_256( x @ W1^T + b1 ) * g1 + be1
// 512 thr, tile M=128 N=256 K=128, 3 split passes, pipelined fragments.
// =====================================================================
#define PK1  136
#define RB1  272
#define G1_AH   0
#define G1_AL   34816
#define G1_BH   69632
#define G1_BL   139264
#define G1_PB   208896
#define G1_PG   209920
#define G1_PE   210944
#define G1_RED  211968
#define G1_MI   216064
#define G1_SMEM 217088

__global__ __launch_bounds__(512, 1)
void gemm1_ln_kernel(const float* __restrict__ x, const float* __restrict__ b1,
                     const float* __restrict__ g1, const float* __restrict__ be1)
{
    extern __shared__ char smem[];
    const uint32_t sb = smem_u32(smem);
    const int tid = threadIdx.x;
    const int row0 = blockIdx.x * 128;

    // stage B images via cp.async (69632 B each = 4352 x 16B)
    for (int i = tid; i < 4352; i += 512) {
        CP16(sb + G1_BH + (uint32_t)i * 16u, (const char*)g_W1h + (size_t)i * 16);
        CP16(sb + G1_BL + (uint32_t)i * 16u, (const char*)g_W1l + (size_t)i * 16);
    }
    CP_COMMIT();

    // stage A: load x fp32, split hi/lo, store padded
    {
        const int r = tid >> 2, q = (tid & 3) * 32;
        const float4* xs = (const float4*)(x + (size_t)(row0 + r) * 128 + q);
        __half* pH = (__half*)(smem + G1_AH) + r * PK1 + q;
        __half* pL = (__half*)(smem + G1_AL) + r * PK1 + q;
        #pragma unroll
        for (int i = 0; i < 8; ++i) {
            float4 f = xs[i];
            __half h0, h1, h2, h3, l0, l1, l2, l3;
            split2(f.x, h0, l0); split2(f.y, h1, l1);
            split2(f.z, h2, l2); split2(f.w, h3, l3);
            *(__half2*)(pH + i * 4)     = __halves2half2(h0, h1);
            *(__half2*)(pH + i * 4 + 2) = __halves2half2(h2, h3);
            *(__half2*)(pL + i * 4)     = __halves2half2(l0, l1);
            *(__half2*)(pL + i * 4 + 2) = __halves2half2(l2, l3);
        }
    }
    if (tid < 256) {
        ((float*)(smem + G1_PB))[tid] = b1[tid];
        ((float*)(smem + G1_PG))[tid] = g1[tid];
        ((float*)(smem + G1_PE))[tid] = be1[tid];
    }
    CP_WAIT0();
    __syncthreads();

    // --- compute ---
    const int wid = tid >> 5, lane = tid & 31;
    const int wm = wid >> 2, wn = wid & 3;
    const int grp = lane >> 3, l7 = lane & 7;

    uint32_t aAh[2], aAl[2], aBh[4], aBl[4];
    #pragma unroll
    for (int mi = 0; mi < 2; ++mi) {
        const int rm = wm * 32 + mi * 16 + (grp & 1) * 8 + l7;
        aAh[mi] = sb + G1_AH + (uint32_t)rm * RB1 + (grp >> 1) * 16;
        aAl[mi] = sb + G1_AL + (uint32_t)rm * RB1 + (grp >> 1) * 16;
    }
    #pragma unroll
    for (int p = 0; p < 4; ++p) {
        const int rn = wn * 64 + p * 16 + (grp >> 1) * 8 + l7;
        aBh[p] = sb + G1_BH + (uint32_t)rn * RB1 + (grp & 1) * 16;
        aBl[p] = sb + G1_BL + (uint32_t)rn * RB1 + (grp & 1) * 16;
    }

    float acc[2][8][4];
    #pragma unroll
    for (int i = 0; i < 2; ++i)
        #pragma unroll
        for (int j = 0; j < 8; ++j)
            #pragma unroll
            for (int c = 0; c < 4; ++c) acc[i][j][c] = 0.f;

    uint32_t bh[2][4], bl[2][4];   // double-buffered B fragments
    #pragma unroll
    for (int s = 0; s < 8; ++s) {
        const uint32_t kb = (uint32_t)s * 32u;
        uint32_t ah0[4], ah1[4], al0[4], al1[4];
        ldsm4(ah0, aAh[0] + kb); ldsm4(ah1, aAh[1] + kb);
        ldsm4(al0, aAl[0] + kb); ldsm4(al1, aAl[1] + kb);
        ldsm4(bh[0], aBh[0] + kb); ldsm4(bl[0], aBl[0] + kb);
        #pragma unroll
        for (int p = 0; p < 4; ++p) {
            const int cur = p & 1, nxt = cur ^ 1;
            if (p < 3) { ldsm4(bh[nxt], aBh[p + 1] + kb); ldsm4(bl[nxt], aBl[p + 1] + kb); }
            uint32_t* tb = bh[cur];
            uint32_t* tl = bl[cur];
            mma16816(acc[0][2 * p], ah0, tb);     mma16816(acc[1][2 * p], ah1, tb);
            mma16816(acc[0][2 * p], ah0, tl);     mma16816(acc[1][2 * p], ah1, tl);
            mma16816(acc[0][2 * p], al0, tb);     mma16816(acc[1][2 * p], al1, tb);
            mma16816(acc[0][2 * p + 1], ah0, tb + 2); mma16816(acc[1][2 * p + 1], ah1, tb + 2);
            mma16816(acc[0][2 * p + 1], ah0, tl + 2); mma16816(acc[1][2 * p + 1], ah1, tl + 2);
            mma16816(acc[0][2 * p + 1], al0, tb + 2); mma16816(acc[1][2 * p + 1], al1, tb + 2);
        }
    }

    // --- LN epilogue ---
    const float* sB = (const float*)(smem + G1_PB);
    const float* sG = (const float*)(smem + G1_PG);
    const float* sE = (const float*)(smem + G1_PE);
    float* RED = (float*)(smem + G1_RED);
    float* MI  = (float*)(smem + G1_MI);
    const int r4 = lane >> 2, cq = (lane & 3) * 2;

    #pragma unroll
    for (int mi = 0; mi < 2; ++mi)
        #pragma unroll
        for (int h = 0; h < 2; ++h) {
            const int rl = wm * 32 + mi * 16 + h * 8 + r4;
            float s = 0.f, sq = 0.f;
            #pragma unroll
            for (int ni = 0; ni < 8; ++ni) {
                const int c = wn * 64 + ni * 8 + cq;
                const float v0 = acc[mi][ni][2 * h] + sB[c];
                const float v1 = acc[mi][ni][2 * h + 1] + sB[c + 1];
                s += v0 + v1; sq += v0 * v0 + v1 * v1;
            }
            s  += __shfl_xor_sync(0xffffffffu, s, 1);
            sq += __shfl_xor_sync(0xffffffffu, sq, 1);
            s  += __shfl_xor_sync(0xffffffffu, s, 2);
            sq += __shfl_xor_sync(0xffffffffu, sq, 2);
            if ((lane & 3) == 0) {
                RED[rl * 8 + wn * 2]     = s;
                RED[rl * 8 + wn * 2 + 1] = sq;
            }
        }
    __syncthreads();
    if (tid < 128) {
        float s = 0.f, sq = 0.f;
        #pragma unroll
        for (int w = 0; w < 4; ++w) { s += RED[tid * 8 + w * 2]; sq += RED[tid * 8 + w * 2 + 1]; }
        const float m   = s * (1.0f / 256.0f);
        const float var = sq * (1.0f / 256.0f) - m * m;
        MI[tid * 2]     = m;
        MI[tid * 2 + 1] = rsqrtf(var + 1e-5f);
    }
    __syncthreads();
    #pragma unroll
    for (int mi = 0; mi < 2; ++mi)
        #pragma unroll
        for (int h = 0; h < 2; ++h) {
            const int rl = wm * 32 + mi * 16 + h * 8 + r4;
            const float m = MI[rl * 2], inv = MI[rl * 2 + 1];
            float* dst = g_h + (size_t)(row0 + rl) * 256;
            #pragma unroll
            for (int ni = 0; ni < 8; ++ni) {
                const int c = wn * 64 + ni * 8 + cq;
                const float v0 = acc[mi][ni][2 * h] + sB[c];
                const float v1 = acc[mi][ni][2 * h + 1] + sB[c + 1];
                float2 o;
                o.x = (v0 - m) * inv * sG[c] + sE[c];
                o.y = (v1 - m) * inv * sG[c + 1] + sE[c + 1];
                *(float2*)(dst + c) = o;
            }
        }
}

// =====================================================================
// LIF1: scan over T; grid (B, 2) x 128 thr, each block does 128 H-cols.
// =====================================================================
__global__ __launch_bounds__(128, 3)
void lif1_kernel()
{
    extern __shared__ float sm[];  // 2 x (64 x 128) f32 = 64KB
    const int b = blockIdx.x, tid = threadIdx.x;
    const int c0 = blockIdx.y * 128;
    const size_t base = (size_t)b * T_ * H_ + c0;
    const uint32_t sb = smem_u32(sm);

    auto prefetch = [&](int c) {
        const float* src = g_h + base + (size_t)c * 64 * H_;
        const uint32_t dst = sb + (uint32_t)(c & 1) * 32768u;
        #pragma unroll
        for (int i = 0; i < 16; ++i) {
            const int u = i * 128 + tid;            // 0..2047 16B vecs
            const int row = u >> 5, v = u & 31;
            CP16(dst + (uint32_t)u * 16u, src + (size_t)row * H_ + v * 4);
        }
    };
    prefetch(0); CP_COMMIT();
    float v = 0.f;
    for (int c = 0; c < 4; ++c) {
        if (c < 3) { prefetch(c + 1); CP_COMMIT(); CP_WAIT1(); }
        else       { CP_WAIT0(); }
        __syncthreads();
        const float* buf = sm + (c & 1) * 8192;
        __half* dst = g_s1 + base + (size_t)c * 64 * H_ + tid;
        #pragma unroll 8
        for (int t = 0; t < 64; ++t) {
            const float xv = buf[t * 128 + tid];
            const float hm = v + (xv - v) * 0.5f;
            const bool  s  = (hm >= 1.0f);
            dst[(size_t)t * H_] = s ? __float2half(1.0f) : __float2half(0.0f);
            v = s ? 0.f : hm;
        }
        __syncthreads();
    }
}

// =====================================================================
// GEMM2 + LN : g_o = LN_128( s1 @ W2^T + b2 ) * g2 + be2
// 512 thr, tile M=128 N=128 K=256, 2 passes (A exact fp16), pipelined.
// =====================================================================
#define PK2  264
#define RB2  528
#define G2_AS   0
#define G2_BH   67584
#define G2_BL   135168
#define G2_PB   202752
#define G2_PG   203264
#define G2_PE   203776
#define G2_RED  204288
#define G2_MI   208384
#define G2_SMEM 209408

__global__ __launch_bounds__(512, 1)
void gemm2_ln_kernel(const float* __restrict__ b2, const float* __restrict__ g2,
                     const float* __restrict__ be2)
{
    extern __shared__ char smem[];
    const uint32_t sb = smem_u32(smem);
    const int tid = threadIdx.x;
    const int row0 = blockIdx.x * 128;

    for (int i = tid; i < 4096; i += 512) {
        const int r = i >> 5, c = i & 31;
        CP16(sb + G2_AS + (uint32_t)(r * RB2 + c * 16),
             g_s1 + (size_t)(row0 + r) * 256 + c * 8);
    }
    for (int i = tid; i < 4224; i += 512) {
        CP16(sb + G2_BH + (uint32_t)i * 16u, (const char*)g_W2h + (size_t)i * 16);
        CP16(sb + G2_BL + (uint32_t)i * 16u, (const char*)g_W2l + (size_t)i * 16);
    }
    CP_COMMIT();
    if (tid < 128) {
        ((float*)(smem + G2_PB))[tid] = b2[tid];
        ((float*)(smem + G2_PG))[tid] = g2[tid];
        ((float*)(smem + G2_PE))[tid] = be2[tid];
    }
    CP_WAIT0();
    __syncthreads();

    const int wid = tid >> 5, lane = tid & 31;
    const int wm = wid >> 2, wn = wid & 3;
    const int grp = lane >> 3, l7 = lane & 7;

    uint32_t aA[2], aBh[2], aBl[2];
    #pragma unroll
    for (int mi = 0; mi < 2; ++mi) {
        const int rm = wm * 32 + mi * 16 + (grp & 1) * 8 + l7;
        aA[mi] = sb + G2_AS + (uint32_t)rm * RB2 + (grp >> 1) * 16;
    }
    #pragma unroll
    for (int p = 0; p < 2; ++p) {
        const int rn = wn * 32 + p * 16 + (grp >> 1) * 8 + l7;
        aBh[p] = sb + G2_BH + (uint32_t)rn * RB2 + (grp & 1) * 16;
        aBl[p] = sb + G2_BL + (uint32_t)rn * RB2 + (grp & 1) * 16;
    }

    float acc[2][4][4];
    #pragma unroll
    for (int i = 0; i < 2; ++i)
        #pragma unroll
        for (int j = 0; j < 4; ++j)
            #pragma unroll
            for (int c = 0; c < 4; ++c) acc[i][j][c] = 0.f;

    uint32_t bh[2][4], bl[2][4];
    #pragma unroll
    for (int s = 0; s < 16; ++s) {
        const uint32_t kb = (uint32_t)s * 32u;
        uint32_t a0[4], a1[4];
        ldsm4(a0, aA[0] + kb); ldsm4(a1, aA[1] + kb);
        ldsm4(bh[0], aBh[0] + kb); ldsm4(bl[0], aBl[0] + kb);
        #pragma unroll
        for (int p = 0; p < 2; ++p) {
            const int cur = p & 1, nxt = cur ^ 1;
            if (p < 1) { ldsm4(bh[nxt], aBh[1] + kb); ldsm4(bl[nxt], aBl[1] + kb); }
            uint32_t* tb = bh[cur];
            uint32_t* tl = bl[cur];
            mma16816(acc[0][2 * p], a0, tb);     mma16816(acc[1][2 * p], a1, tb);
            mma16816(acc[0][2 * p], a0, tl);     mma16816(acc[1][2 * p], a1, tl);
            mma16816(acc[0][2 * p + 1], a0, tb + 2); mma16816(acc[1][2 * p + 1], a1, tb + 2);
            mma16816(acc[0][2 * p + 1], a0, tl + 2); mma16816(acc[1][2 * p + 1], a1, tl + 2);
        }
    }

    // --- LN epilogue over D=128 ---
    const float* sB = (const float*)(smem + G2_PB);
    const float* sG = (const float*)(smem + G2_PG);
    const float* sE = (const float*)(smem + G2_PE);
    float* RED = (float*)(smem + G2_RED);
    float* MI  = (float*)(smem + G2_MI);
    const int r4 = lane >> 2, cq = (lane & 3) * 2;

    #pragma unroll
    for (int mi = 0; mi < 2; ++mi)
        #pragma unroll
        for (int h = 0; h < 2; ++h) {
            const int rl = wm * 32 + mi * 16 + h * 8 + r4;
            float s = 0.f, sq = 0.f;
            #pragma unroll
            for (int ni = 0; ni < 4; ++ni) {
                const int c = wn * 32 + ni * 8 + cq;
                const float v0 = acc[mi][ni][2 * h] + sB[c];
                const float v1 = acc[mi][ni][2 * h + 1] + sB[c + 1];
                s += v0 + v1; sq += v0 * v0 + v1 * v1;
            }
            s  += __shfl_xor_sync(0xffffffffu, s, 1);
            sq += __shfl_xor_sync(0xffffffffu, sq, 1);
            s  += __shfl_xor_sync(0xffffffffu, s, 2);
            sq += __shfl_xor_sync(0xffffffffu, sq, 2);
            if ((lane & 3) == 0) {
                RED[rl * 8 + wn * 2]     = s;
                RED[rl * 8 + wn * 2 + 1] = sq;
            }
        }
    __syncthreads();
    if (tid < 128) {
        float s = 0.f, sq = 0.f;
        #pragma unroll
        for (int w = 0; w < 4; ++w) { s += RED[tid * 8 + w * 2]; sq += RED[tid * 8 + w * 2 + 1]; }
        const float m   = s * (1.0f / 128.0f);
        const float var = sq * (1.0f / 128.0f) - m * m;
        MI[tid * 2]     = m;
        MI[tid * 2 + 1] = rsqrtf(var + 1e-5f);
    }
    __syncthreads();
    #pragma unroll
    for (int mi = 0; mi < 2; ++mi)
        #pragma unroll
        for (int h = 0; h < 2; ++h) {
            const int rl = wm * 32 + mi * 16 + h * 8 + r4;
            const float m = MI[rl * 2], inv = MI[rl * 2 + 1];
            float* dst = g_o + (size_t)(row0 + rl) * 128;
            #pragma unroll
            for (int ni = 0; ni < 4; ++ni) {
                const int c = wn * 32 + ni * 8 + cq;
                const float v0 = acc[mi][ni][2 * h] + sB[c];
                const float v1 = acc[mi][ni][2 * h + 1] + sB[c + 1];
                float2 o;
                o.x = (v0 - m) * inv * sG[c] + sE[c];
                o.y = (v1 - m) * inv * sG[c + 1] + sE[c + 1];
                *(float2*)(dst + c) = o;
            }
        }
}

// =====================================================================
// LIF2 + residual: grid (B, 2) x 64 thr, each block does 64 D-cols.
// =====================================================================
__global__ __launch_bounds__(64, 3)
void lif2_res_kernel(const float* __restrict__ x, float* __restrict__ out)
{
    extern __shared__ float sm[];  // 2 x (16KB o + 16KB x) = 64KB
    const int b = blockIdx.x, tid = threadIdx.x;
    const int c0 = blockIdx.y * 64;
    const size_t base = (size_t)b * T_ * D_ + c0;
    const uint32_t sb = smem_u32(sm);

    auto prefetch = [&](int c) {
        const float* so = g_o + base + (size_t)c * 64 * D_;
        const float* sx = x   + base + (size_t)c * 64 * D_;
        const uint32_t d0 = sb + (uint32_t)(c & 1) * 32768u;
        #pragma unroll
        for (int i = 0; i < 16; ++i) {
            const int u = i * 64 + tid;             // 0..1023 16B vecs
            const int row = u >> 4, v = u & 15;
            CP16(d0 + (uint32_t)u * 16u, so + (size_t)row * D_ + v * 4);
            CP16(d0 + 16384u + (uint32_t)u * 16u, sx + (size_t)row * D_ + v * 4);
        }
    };
    prefetch(0); CP_COMMIT();
    float v = 0.f;
    for (int c = 0; c < 4; ++c) {
        if (c < 3) { prefetch(c + 1); CP_COMMIT(); CP_WAIT1(); }
        else       { CP_WAIT0(); }
        __syncthreads();
        const float* bo = sm + (c & 1) * 8192;
        const float* bx = bo + 4096;
        float* dst = out + base + (size_t)c * 64 * D_ + tid;
        #pragma unroll 8
        for (int t = 0; t < 64; ++t) {
            const float ov = bo[t * 64 + tid];
            const float hm = v + (ov - v) * 0.5f;
            const bool  s  = (hm >= 1.0f);
            v = s ? 0.f : hm;
            dst[(size_t)t * D_] = bx[t * 64 + tid] + (s ? 1.0f : 0.0f);
        }
        __syncthreads();
    }
}

// =====================================================================
extern "C" void kernel_launch(void* const* d_in, const int* in_sizes, int n_in,
                              void* d_out, int out_size)
{
    const float* x   = (const float*)d_in[0];
    const float* W1  = (const float*)d_in[1];
    const float* b1  = (const float*)d_in[2];
    const float* g1  = (const float*)d_in[3];
    const float* be1 = (const float*)d_in[4];
    const float* W2  = (const float*)d_in[5];
    const float* b2  = (const float*)d_in[6];
    const float* g2  = (const float*)d_in[7];
    const float* be2 = (const float*)d_in[8];
    float* out = (float*)d_out;

    static const bool _cfg = []() {
        cudaFuncSetAttribute(gemm1_ln_kernel, cudaFuncAttributeMaxDynamicSharedMemorySize, G1_SMEM);
        cudaFuncSetAttribute(gemm2_ln_kernel, cudaFuncAttributeMaxDynamicSharedMemorySize, G2_SMEM);
        cudaFuncSetAttribute(lif1_kernel,     cudaFuncAttributeMaxDynamicSharedMemorySize, 65536);
        cudaFuncSetAttribute(lif2_res_kernel, cudaFuncAttributeMaxDynamicSharedMemorySize, 65536);
        return true;
    }();
    (void)_cfg; (void)in_sizes; (void)n_in; (void)out_size;

    prep_kernel<<<128, 256>>>(W1, W2);
    gemm1_ln_kernel<<<BT_ / 128, 512, G1_SMEM>>>(x, b1, g1, be1);
    lif1_kernel<<<dim3(B_, 2), 128, 65536>>>();
    gemm2_ln_kernel<<<BT_ / 128, 512, G2_SMEM>>>(b2, g2, be2);
    lif2_res_kernel<<<dim3(B_, 2), 64, 65536>>>(x, out);
}

// round 7
// speedup vs baseline: 3.4294x; 1.0972x over previous
#include <cuda_runtime.h>
#include <cuda_fp16.h>
#include <cstdint>
#include <cstddef>

#define B_  256
#define T_  256
#define D_  128
#define H_  256
#define BT_ 65536

// ---------------- global scratch ----------------
__device__ float  g_h [(size_t)BT_ * H_];   // post-LN hidden  [BT,256] fp32
__device__ __half g_s1[(size_t)BT_ * H_];   // layer-1 spikes  [BT,256] fp16 exact {0,1}
__device__ float  g_o [(size_t)BT_ * D_];   // post-LN output  [BT,128] fp32
__device__ __align__(16) __half g_W1h[256 * 136];
__device__ __align__(16) __half g_W1l[256 * 136];
__device__ __align__(16) __half g_W2h[128 * 264];
__device__ __align__(16) __half g_W2l[128 * 264];

// ---------------- helpers ----------------
__device__ __forceinline__ uint32_t smem_u32(const void* p) {
    uint32_t a;
    asm("{ .reg .u64 t; cvta.to.shared.u64 t, %1; cvt.u32.u64 %0, t; }" : "=r"(a) : "l"(p));
    return a;
}
#define CP16(dst, src) asm volatile("cp.async.cg.shared.global [%0], [%1], 16;" :: "r"(dst), "l"(src))
#define CP_COMMIT()    asm volatile("cp.async.commit_group;" ::: "memory")
#define CP_WAIT0()     asm volatile("cp.async.wait_group 0;" ::: "memory")
#define CP_WAIT1()     asm volatile("cp.async.wait_group 1;" ::: "memory")

__device__ __forceinline__ void ldsm4(uint32_t* r, uint32_t addr) {
    asm volatile("ldmatrix.sync.aligned.m8n8.x4.shared.b16 {%0,%1,%2,%3}, [%4];"
                 : "=r"(r[0]), "=r"(r[1]), "=r"(r[2]), "=r"(r[3]) : "r"(addr));
}
__device__ __forceinline__ void mma16816(float* d, const uint32_t* a, const uint32_t* b) {
    asm volatile("mma.sync.aligned.m16n8k16.row.col.f32.f16.f16.f32 "
                 "{%0,%1,%2,%3}, {%4,%5,%6,%7}, {%8,%9}, {%0,%1,%2,%3};"
                 : "+f"(d[0]), "+f"(d[1]), "+f"(d[2]), "+f"(d[3])
                 : "r"(a[0]), "r"(a[1]), "r"(a[2]), "r"(a[3]), "r"(b[0]), "r"(b[1]));
}
__device__ __forceinline__ void split2(float f, __half& hi, __half& lo) {
    hi = __float2half_rn(f);
    lo = __float2half_rn(f - __half2float(hi));
}

// =====================================================================
// Prep: split W1/W2 into fp16 hi/lo padded images
// =====================================================================
__global__ void prep_kernel(const float* __restrict__ W1, const float* __restrict__ W2)
{
    const int idx = blockIdx.x * blockDim.x + threadIdx.x;  // 0..32767
    {
        const int n = idx >> 7, k = idx & 127;
        __half hi, lo; split2(W1[idx], hi, lo);
        g_W1h[n * 136 + k] = hi;
        g_W1l[n * 136 + k] = lo;
    }
    {
        const int n = idx >> 8, k = idx & 255;
        __half hi, lo; split2(W2[idx], hi, lo);
        g_W2h[n * 264 + k] = hi;
        g_W2l[n * 264 + k] = lo;
    }
}

// =====================================================================
// GEMM1 + LN (persistent): 128 blocks x 8 tiles of M=64, N=256, K=128.
// Weights staged once/block; next x tile LDG-prefetched during compute.
// =====================================================================
#define RB1  272
#define G1_BH   0
#define G1_BL   69632
#define G1_A_H  139264
#define G1_A_L  156672
#define G1_PB   174080
#define G1_PG   175104
#define G1_PE   176128
#define G1_RED  177152
#define G1_MI   181248
#define G1_SMEM 181760

__global__ __launch_bounds__(512, 1)
void gemm1_ln_kernel(const float* __restrict__ x, const float* __restrict__ b1,
                     const float* __restrict__ g1, const float* __restrict__ be1)
{
    extern __shared__ char smem[];
    const uint32_t sb = smem_u32(smem);
    const int tid = threadIdx.x;

    // stage weight images once (4352 x 16B each)
    for (int i = tid; i < 4352; i += 512) {
        CP16(sb + G1_BH + (uint32_t)i * 16u, (const char*)g_W1h + (size_t)i * 16);
        CP16(sb + G1_BL + (uint32_t)i * 16u, (const char*)g_W1l + (size_t)i * 16);
    }
    CP_COMMIT();
    if (tid < 256) {
        ((float*)(smem + G1_PB))[tid] = b1[tid];
        ((float*)(smem + G1_PG))[tid] = g1[tid];
        ((float*)(smem + G1_PE))[tid] = be1[tid];
    }

    const int wid = tid >> 5, lane = tid & 31;
    const int wm = wid & 1, wn = wid >> 1;           // wm: M-half, wn: 0..7 N-slice (32 cols)
    const int grp = lane >> 3, l7 = lane & 7;
    const int r4 = lane >> 2, cq = (lane & 3) * 2;

    // per-thread staging geometry: row r (0..63), 16 cols at q
    const int r_st = tid >> 3, q_st = (tid & 7) * 16;

    uint32_t aAh[2], aAl[2], aBh[2], aBl[2];
    #pragma unroll
    for (int mi = 0; mi < 2; ++mi) {
        const int rm = wm * 32 + mi * 16 + (grp & 1) * 8 + l7;
        aAh[mi] = sb + G1_A_H + (uint32_t)rm * RB1 + (grp >> 1) * 16;
        aAl[mi] = sb + G1_A_L + (uint32_t)rm * RB1 + (grp >> 1) * 16;
    }
    #pragma unroll
    for (int p = 0; p < 2; ++p) {
        const int rn = wn * 32 + p * 16 + (grp >> 1) * 8 + l7;
        aBh[p] = sb + G1_BH + (uint32_t)rn * RB1 + (grp & 1) * 16;
        aBl[p] = sb + G1_BL + (uint32_t)rn * RB1 + (grp & 1) * 16;
    }

    const float* sB = (const float*)(smem + G1_PB);
    const float* sG = (const float*)(smem + G1_PG);
    const float* sE = (const float*)(smem + G1_PE);
    float* RED = (float*)(smem + G1_RED);
    float* MI  = (float*)(smem + G1_MI);

    // prefetch tile 0 x regs
    float4 xr[4];
    {
        const int row0 = blockIdx.x * 64;
        const float4* xs = (const float4*)(x + (size_t)(row0 + r_st) * 128 + q_st);
        #pragma unroll
        for (int i = 0; i < 4; ++i) xr[i] = xs[i];
    }
    CP_WAIT0();
    __syncthreads();

    for (int it = 0; it < 8; ++it) {
        const int tidx = blockIdx.x + it * 128;      // tile index 0..1023
        const int row0 = tidx * 64;

        // convert + store staged regs -> A
        {
            __half* pH = (__half*)(smem + G1_A_H) + r_st * 136 + q_st;
            __half* pL = (__half*)(smem + G1_A_L) + r_st * 136 + q_st;
            #pragma unroll
            for (int i = 0; i < 4; ++i) {
                float4 f = xr[i];
                __half h0, h1, h2, h3, l0, l1, l2, l3;
                split2(f.x, h0, l0); split2(f.y, h1, l1);
                split2(f.z, h2, l2); split2(f.w, h3, l3);
                __half2 A = __halves2half2(h0, h1), Bv = __halves2half2(h2, h3);
                __half2 C = __halves2half2(l0, l1), Dv = __halves2half2(l2, l3);
                *(uint2*)(pH + i * 4) = make_uint2(*(uint32_t*)&A, *(uint32_t*)&Bv);
                *(uint2*)(pL + i * 4) = make_uint2(*(uint32_t*)&C, *(uint32_t*)&Dv);
            }
        }
        __syncthreads();

        // prefetch next tile's x into regs (overlaps compute)
        if (it < 7) {
            const int nrow0 = (blockIdx.x + (it + 1) * 128) * 64;
            const float4* xs = (const float4*)(x + (size_t)(nrow0 + r_st) * 128 + q_st);
            #pragma unroll
            for (int i = 0; i < 4; ++i) xr[i] = xs[i];
        }

        // ---- compute ----
        float acc[2][4][4];
        #pragma unroll
        for (int i = 0; i < 2; ++i)
            #pragma unroll
            for (int j = 0; j < 4; ++j)
                #pragma unroll
                for (int c = 0; c < 4; ++c) acc[i][j][c] = 0.f;

        #pragma unroll
        for (int s = 0; s < 8; ++s) {
            const uint32_t kb = (uint32_t)s * 32u;
            uint32_t ah0[4], ah1[4], al0[4], al1[4];
            ldsm4(ah0, aAh[0] + kb); ldsm4(ah1, aAh[1] + kb);
            ldsm4(al0, aAl[0] + kb); ldsm4(al1, aAl[1] + kb);
            #pragma unroll
            for (int p = 0; p < 2; ++p) {
                uint32_t tb[4], tl[4];
                ldsm4(tb, aBh[p] + kb);
                ldsm4(tl, aBl[p] + kb);
                mma16816(acc[0][2 * p], ah0, tb);     mma16816(acc[1][2 * p], ah1, tb);
                mma16816(acc[0][2 * p], ah0, tl);     mma16816(acc[1][2 * p], ah1, tl);
                mma16816(acc[0][2 * p], al0, tb);     mma16816(acc[1][2 * p], al1, tb);
                mma16816(acc[0][2 * p + 1], ah0, tb + 2); mma16816(acc[1][2 * p + 1], ah1, tb + 2);
                mma16816(acc[0][2 * p + 1], ah0, tl + 2); mma16816(acc[1][2 * p + 1], ah1, tl + 2);
                mma16816(acc[0][2 * p + 1], al0, tb + 2); mma16816(acc[1][2 * p + 1], al1, tb + 2);
            }
        }

        // ---- LN epilogue ----
        #pragma unroll
        for (int mi = 0; mi < 2; ++mi)
            #pragma unroll
            for (int h = 0; h < 2; ++h) {
                const int rl = wm * 32 + mi * 16 + h * 8 + r4;
                float s = 0.f, sq = 0.f;
                #pragma unroll
                for (int ni = 0; ni < 4; ++ni) {
                    const int c = wn * 32 + ni * 8 + cq;
                    const float v0 = acc[mi][ni][2 * h] + sB[c];
                    const float v1 = acc[mi][ni][2 * h + 1] + sB[c + 1];
                    s += v0 + v1; sq += v0 * v0 + v1 * v1;
                }
                s  += __shfl_xor_sync(0xffffffffu, s, 1);
                sq += __shfl_xor_sync(0xffffffffu, sq, 1);
                s  += __shfl_xor_sync(0xffffffffu, s, 2);
                sq += __shfl_xor_sync(0xffffffffu, sq, 2);
                if ((lane & 3) == 0) {
                    RED[rl * 16 + wn * 2]     = s;
                    RED[rl * 16 + wn * 2 + 1] = sq;
                }
            }
        __syncthreads();
        if (tid < 64) {
            float s = 0.f, sq = 0.f;
            #pragma unroll
            for (int w = 0; w < 8; ++w) { s += RED[tid * 16 + w * 2]; sq += RED[tid * 16 + w * 2 + 1]; }
            const float m   = s * (1.0f / 256.0f);
            const float var = sq * (1.0f / 256.0f) - m * m;
            MI[tid * 2]     = m;
            MI[tid * 2 + 1] = rsqrtf(var + 1e-5f);
        }
        __syncthreads();
        #pragma unroll
        for (int mi = 0; mi < 2; ++mi)
            #pragma unroll
            for (int h = 0; h < 2; ++h) {
                const int rl = wm * 32 + mi * 16 + h * 8 + r4;
                const float m = MI[rl * 2], inv = MI[rl * 2 + 1];
                float* dst = g_h + (size_t)(row0 + rl) * 256;
                #pragma unroll
                for (int ni = 0; ni < 4; ++ni) {
                    const int c = wn * 32 + ni * 8 + cq;
                    const float v0 = acc[mi][ni][2 * h] + sB[c];
                    const float v1 = acc[mi][ni][2 * h + 1] + sB[c + 1];
                    float2 o;
                    o.x = (v0 - m) * inv * sG[c] + sE[c];
                    o.y = (v1 - m) * inv * sG[c + 1] + sE[c + 1];
                    *(float2*)(dst + c) = o;
                }
            }
        __syncthreads();
    }
}

// =====================================================================
// LIF1: scan over T; grid (B, 2) x 128 thr, each block does 128 H-cols.
// =====================================================================
__global__ __launch_bounds__(128, 3)
void lif1_kernel()
{
    extern __shared__ float sm[];
    const int b = blockIdx.x, tid = threadIdx.x;
    const int c0 = blockIdx.y * 128;
    const size_t base = (size_t)b * T_ * H_ + c0;
    const uint32_t sb = smem_u32(sm);

    auto prefetch = [&](int c) {
        const float* src = g_h + base + (size_t)c * 64 * H_;
        const uint32_t dst = sb + (uint32_t)(c & 1) * 32768u;
        #pragma unroll
        for (int i = 0; i < 16; ++i) {
            const int u = i * 128 + tid;
            const int row = u >> 5, v = u & 31;
            CP16(dst + (uint32_t)u * 16u, src + (size_t)row * H_ + v * 4);
        }
    };
    prefetch(0); CP_COMMIT();
    float v = 0.f;
    for (int c = 0; c < 4; ++c) {
        if (c < 3) { prefetch(c + 1); CP_COMMIT(); CP_WAIT1(); }
        else       { CP_WAIT0(); }
        __syncthreads();
        const float* buf = sm + (c & 1) * 8192;
        __half* dst = g_s1 + base + (size_t)c * 64 * H_ + tid;
        #pragma unroll 8
        for (int t = 0; t < 64; ++t) {
            const float xv = buf[t * 128 + tid];
            const float hm = v + (xv - v) * 0.5f;
            const bool  s  = (hm >= 1.0f);
            dst[(size_t)t * H_] = s ? __float2half(1.0f) : __float2half(0.0f);
            v = s ? 0.f : hm;
        }
        __syncthreads();
    }
}

// =====================================================================
// GEMM2 + LN (persistent): 128 blocks x 8 tiles of M=64, N=128, K=256.
// Weights staged once; A (spikes) cp.async double-buffered.
// =====================================================================
#define RB2  528
#define G2_BH   0
#define G2_BL   67584
#define G2_A0   135168
#define G2_A1   168960
#define G2_PB   202752
#define G2_PG   203264
#define G2_PE   203776
#define G2_RED  204288
#define G2_MI   208384
#define G2_SMEM 208896

__global__ __launch_bounds__(512, 1)
void gemm2_ln_kernel(const float* __restrict__ b2, const float* __restrict__ g2,
                     const float* __restrict__ be2)
{
    extern __shared__ char smem[];
    const uint32_t sb = smem_u32(smem);
    const int tid = threadIdx.x;

    // stage weights once (4224 x 16B each)
    for (int i = tid; i < 4224; i += 512) {
        CP16(sb + G2_BH + (uint32_t)i * 16u, (const char*)g_W2h + (size_t)i * 16);
        CP16(sb + G2_BL + (uint32_t)i * 16u, (const char*)g_W2l + (size_t)i * 16);
    }
    // stage A tile 0 into buf 0 (2048 x 16B)
    {
        const int row0 = blockIdx.x * 64;
        #pragma unroll
        for (int j = 0; j < 4; ++j) {
            const int u = tid + j * 512;
            const int row = u >> 5, cvi = u & 31;
            CP16(sb + G2_A0 + (uint32_t)(row * RB2 + cvi * 16),
                 g_s1 + (size_t)(row0 + row) * 256 + cvi * 8);
        }
    }
    CP_COMMIT();
    if (tid < 128) {
        ((float*)(smem + G2_PB))[tid] = b2[tid];
        ((float*)(smem + G2_PG))[tid] = g2[tid];
        ((float*)(smem + G2_PE))[tid] = be2[tid];
    }

    const int wid = tid >> 5, lane = tid & 31;
    const int wm = wid & 1, wn = wid >> 1;           // wm: M-half, wn: 0..7 (16 cols)
    const int grp = lane >> 3, l7 = lane & 7;
    const int r4 = lane >> 2, cq = (lane & 3) * 2;

    uint32_t aBh, aBl;
    {
        const int rn = wn * 16 + (grp >> 1) * 8 + l7;
        aBh = sb + G2_BH + (uint32_t)rn * RB2 + (grp & 1) * 16;
        aBl = sb + G2_BL + (uint32_t)rn * RB2 + (grp & 1) * 16;
    }
    const uint32_t aAoff = (uint32_t)(wm * 32 + (grp & 1) * 8 + l7) * RB2 + (grp >> 1) * 16;

    const float* sB = (const float*)(smem + G2_PB);
    const float* sG = (const float*)(smem + G2_PG);
    const float* sE = (const float*)(smem + G2_PE);
    float* RED = (float*)(smem + G2_RED);
    float* MI  = (float*)(smem + G2_MI);

    CP_WAIT0();
    __syncthreads();

    uint32_t curA = sb + G2_A0, nxtA = sb + G2_A1;
    for (int it = 0; it < 8; ++it) {
        const int row0 = (blockIdx.x + it * 128) * 64;

        // stage next A tile (overlaps compute)
        if (it < 7) {
            const int nrow0 = (blockIdx.x + (it + 1) * 128) * 64;
            #pragma unroll
            for (int j = 0; j < 4; ++j) {
                const int u = tid + j * 512;
                const int row = u >> 5, cvi = u & 31;
                CP16(nxtA + (uint32_t)(row * RB2 + cvi * 16),
                     g_s1 + (size_t)(nrow0 + row) * 256 + cvi * 8);
            }
            CP_COMMIT();
        }

        // ---- compute ----
        float acc[2][2][4];
        #pragma unroll
        for (int i = 0; i < 2; ++i)
            #pragma unroll
            for (int j = 0; j < 2; ++j)
                #pragma unroll
                for (int c = 0; c < 4; ++c) acc[i][j][c] = 0.f;

        #pragma unroll
        for (int s = 0; s < 16; ++s) {
            const uint32_t kb = (uint32_t)s * 32u;
            uint32_t a0[4], a1[4], tb[4], tl[4];
            ldsm4(a0, curA + aAoff + kb);
            ldsm4(a1, curA + aAoff + 16u * RB2 + kb);
            ldsm4(tb, aBh + kb);
            ldsm4(tl, aBl + kb);
            mma16816(acc[0][0], a0, tb);     mma16816(acc[1][0], a1, tb);
            mma16816(acc[0][0], a0, tl);     mma16816(acc[1][0], a1, tl);
            mma16816(acc[0][1], a0, tb + 2); mma16816(acc[1][1], a1, tb + 2);
            mma16816(acc[0][1], a0, tl + 2); mma16816(acc[1][1], a1, tl + 2);
        }

        // ---- LN epilogue over D=128 ----
        #pragma unroll
        for (int mi = 0; mi < 2; ++mi)
            #pragma unroll
            for (int h = 0; h < 2; ++h) {
                const int rl = wm * 32 + mi * 16 + h * 8 + r4;
                float s = 0.f, sq = 0.f;
                #pragma unroll
                for (int ni = 0; ni < 2; ++ni) {
                    const int c = wn * 16 + ni * 8 + cq;
                    const float v0 = acc[mi][ni][2 * h] + sB[c];
                    const float v1 = acc[mi][ni][2 * h + 1] + sB[c + 1];
                    s += v0 + v1; sq += v0 * v0 + v1 * v1;
                }
                s  += __shfl_xor_sync(0xffffffffu, s, 1);
                sq += __shfl_xor_sync(0xffffffffu, sq, 1);
                s  += __shfl_xor_sync(0xffffffffu, s, 2);
                sq += __shfl_xor_sync(0xffffffffu, sq, 2);
                if ((lane & 3) == 0) {
                    RED[rl * 16 + wn * 2]     = s;
                    RED[rl * 16 + wn * 2 + 1] = sq;
                }
            }
        __syncthreads();
        if (tid < 64) {
            float s = 0.f, sq = 0.f;
            #pragma unroll
            for (int w = 0; w < 8; ++w) { s += RED[tid * 16 + w * 2]; sq += RED[tid * 16 + w * 2 + 1]; }
            const float m   = s * (1.0f / 128.0f);
            const float var = sq * (1.0f / 128.0f) - m * m;
            MI[tid * 2]     = m;
            MI[tid * 2 + 1] = rsqrtf(var + 1e-5f);
        }
        __syncthreads();
        #pragma unroll
        for (int mi = 0; mi < 2; ++mi)
            #pragma unroll
            for (int h = 0; h < 2; ++h) {
                const int rl = wm * 32 + mi * 16 + h * 8 + r4;
                const float m = MI[rl * 2], inv = MI[rl * 2 + 1];
                float* dst = g_o + (size_t)(row0 + rl) * 128;
                #pragma unroll
                for (int ni = 0; ni < 2; ++ni) {
                    const int c = wn * 16 + ni * 8 + cq;
                    const float v0 = acc[mi][ni][2 * h] + sB[c];
                    const float v1 = acc[mi][ni][2 * h + 1] + sB[c + 1];
                    float2 o;
                    o.x = (v0 - m) * inv * sG[c] + sE[c];
                    o.y = (v1 - m) * inv * sG[c + 1] + sE[c + 1];
                    *(float2*)(dst + c) = o;
                }
            }
        if (it < 7) { CP_WAIT0(); }
        __syncthreads();
        const uint32_t tmp = curA; curA = nxtA; nxtA = tmp;
    }
}

// =====================================================================
// LIF2 + residual: grid (B, 2) x 64 thr, each block does 64 D-cols.
// =====================================================================
__global__ __launch_bounds__(64, 3)
void lif2_res_kernel(const float* __restrict__ x, float* __restrict__ out)
{
    extern __shared__ float sm[];
    const int b = blockIdx.x, tid = threadIdx.x;
    const int c0 = blockIdx.y * 64;
    const size_t base = (size_t)b * T_ * D_ + c0;
    const uint32_t sb = smem_u32(sm);

    auto prefetch = [&](int c) {
        const float* so = g_o + base + (size_t)c * 64 * D_;
        const float* sx = x   + base + (size_t)c * 64 * D_;
        const uint32_t d0 = sb + (uint32_t)(c & 1) * 32768u;
        #pragma unroll
        for (int i = 0; i < 16; ++i) {
            const int u = i * 64 + tid;
            const int row = u >> 4, v = u & 15;
            CP16(d0 + (uint32_t)u * 16u, so + (size_t)row * D_ + v * 4);
            CP16(d0 + 16384u + (uint32_t)u * 16u, sx + (size_t)row * D_ + v * 4);
        }
    };
    prefetch(0); CP_COMMIT();
    float v = 0.f;
    for (int c = 0; c < 4; ++c) {
        if (c < 3) { prefetch(c + 1); CP_COMMIT(); CP_WAIT1(); }
        else       { CP_WAIT0(); }
        __syncthreads();
        const float* bo = sm + (c & 1) * 8192;
        const float* bx = bo + 4096;
        float* dst = out + base + (size_t)c * 64 * D_ + tid;
        #pragma unroll 8
        for (int t = 0; t < 64; ++t) {
            const float ov = bo[t * 64 + tid];
            const float hm = v + (ov - v) * 0.5f;
            const bool  s  = (hm >= 1.0f);
            v = s ? 0.f : hm;
            dst[(size_t)t * D_] = bx[t * 64 + tid] + (s ? 1.0f : 0.0f);
        }
        __syncthreads();
    }
}

// =====================================================================
extern "C" void kernel_launch(void* const* d_in, const int* in_sizes, int n_in,
                              void* d_out, int out_size)
{
    const float* x   = (const float*)d_in[0];
    const float* W1  = (const float*)d_in[1];
    const float* b1  = (const float*)d_in[2];
    const float* g1  = (const float*)d_in[3];
    const float* be1 = (const float*)d_in[4];
    const float* W2  = (const float*)d_in[5];
    const float* b2  = (const float*)d_in[6];
    const float* g2  = (const float*)d_in[7];
    const float* be2 = (const float*)d_in[8];
    float* out = (float*)d_out;

    static const bool _cfg = []() {
        cudaFuncSetAttribute(gemm1_ln_kernel, cudaFuncAttributeMaxDynamicSharedMemorySize, G1_SMEM);
        cudaFuncSetAttribute(gemm2_ln_kernel, cudaFuncAttributeMaxDynamicSharedMemorySize, G2_SMEM);
        cudaFuncSetAttribute(lif1_kernel,     cudaFuncAttributeMaxDynamicSharedMemorySize, 65536);
        cudaFuncSetAttribute(lif2_res_kernel, cudaFuncAttributeMaxDynamicSharedMemorySize, 65536);
        return true;
    }();
    (void)_cfg; (void)in_sizes; (void)n_in; (void)out_size;

    prep_kernel<<<128, 256>>>(W1, W2);
    gemm1_ln_kernel<<<128, 512, G1_SMEM>>>(x, b1, g1, be1);
    lif1_kernel<<<dim3(B_, 2), 128, 65536>>>();
    gemm2_ln_kernel<<<128, 512, G2_SMEM>>>(b2, g2, be2);
    lif2_res_kernel<<<dim3(B_, 2), 64, 65536>>>(x, out);
}